// round 1
// baseline (speedup 1.0000x reference)
#include <cuda_runtime.h>
#include <cuda_bf16.h>

// TinyTransformerBlock: attention + soft-MoE, all fp32.
// Baseline: smem-tiled SGEMM (128x128x8, 8x8 microtile) with fused epilogues.

#define BM 128
#define BN 128
#define BK 8
#define TM 8
#define TN 8

enum {
    EPI_NONE = 0,
    EPI_SCALE = 1,
    EPI_BIAS = 2,
    EPI_BIAS_RELU = 3,
    EPI_BIAS_RESID = 4,
    EPI_GATED_ACC = 5
};

// ---- scratch (allocation-free; __device__ globals) ----
__device__ float g_q[4096 * 1024];
__device__ float g_k[4096 * 1024];
__device__ float g_v[4096 * 1024];
__device__ float g_s[4 * 1024 * 1024];     // attention scores / probs
__device__ float g_a[4096 * 1024];         // attn @ V
__device__ float g_x2[4096 * 1024];        // x + attn_out  (post-residual)
__device__ float g_g[4096 * 8];            // gates
__device__ float g_h[4096u * 4096u];       // expert hidden (one expert at a time)

template <int EPI, bool TRANSB>
__launch_bounds__(256, 2)
__global__ void sgemm(const float* __restrict__ A, const float* __restrict__ B,
                      float* __restrict__ C, int M, int N, int K,
                      long long sA, long long sB, long long sC,
                      const float* __restrict__ bias,
                      const float* __restrict__ resid,
                      const float* __restrict__ gate, int gateStride,
                      float alpha)
{
    __shared__ float As[BK][BM];
    __shared__ float Bs[BK][BN];

    const int bz = blockIdx.z;
    A += (long long)bz * sA;
    B += (long long)bz * sB;
    C += (long long)bz * sC;

    const int row0 = blockIdx.y * BM;
    const int col0 = blockIdx.x * BN;
    const int tid = threadIdx.x;
    const int tx = tid & 15;        // 0..15  (N direction)
    const int ty = tid >> 4;        // 0..15  (M direction)

    // A tile load mapping: 128 rows x 8 k, one float4 per thread
    const int arow = tid >> 1;            // 0..127
    const int acol = (tid & 1) * 4;       // 0 or 4
    const float* Aptr = A + (long long)(row0 + arow) * K + acol;

    // B tile load mapping
    // NN: B is [K,N]; 8 k-rows x 128 n, one float4 per thread
    const int bnrow = tid >> 5;           // 0..7 (k)
    const int bncol = (tid & 31) * 4;     // 0..124 (n)
    // NT: B is [N,K]; 128 n-rows x 8 k, one float4 per thread
    const int btn = tid >> 1;             // 0..127 (n)
    const int btk = (tid & 1) * 4;        // 0 or 4 (k)

    const float* Bptr;
    if (TRANSB)
        Bptr = B + (long long)(col0 + btn) * K + btk;
    else
        Bptr = B + (long long)bnrow * N + col0 + bncol;

    float acc[TM][TN];
#pragma unroll
    for (int i = 0; i < TM; i++)
#pragma unroll
        for (int j = 0; j < TN; j++) acc[i][j] = 0.0f;

    for (int k0 = 0; k0 < K; k0 += BK) {
        float4 av = *(const float4*)Aptr;
        As[acol + 0][arow] = av.x;
        As[acol + 1][arow] = av.y;
        As[acol + 2][arow] = av.z;
        As[acol + 3][arow] = av.w;

        float4 bv = *(const float4*)Bptr;
        if (TRANSB) {
            Bs[btk + 0][btn] = bv.x;
            Bs[btk + 1][btn] = bv.y;
            Bs[btk + 2][btn] = bv.z;
            Bs[btk + 3][btn] = bv.w;
        } else {
            *(float4*)&Bs[bnrow][bncol] = bv;
        }
        __syncthreads();

#pragma unroll
        for (int kk = 0; kk < BK; kk++) {
            float a[TM], b[TN];
            *(float4*)&a[0] = *(const float4*)&As[kk][ty * TM];
            *(float4*)&a[4] = *(const float4*)&As[kk][ty * TM + 4];
            *(float4*)&b[0] = *(const float4*)&Bs[kk][tx * TN];
            *(float4*)&b[4] = *(const float4*)&Bs[kk][tx * TN + 4];
#pragma unroll
            for (int i = 0; i < TM; i++)
#pragma unroll
                for (int j = 0; j < TN; j++)
                    acc[i][j] = fmaf(a[i], b[j], acc[i][j]);
        }
        __syncthreads();

        Aptr += BK;
        if (TRANSB) Bptr += BK;
        else        Bptr += (long long)BK * N;
    }

    // ---- epilogue ----
#pragma unroll
    for (int i = 0; i < TM; i++) {
        const int m = row0 + ty * TM + i;
        float gm = 0.0f;
        if (EPI == EPI_GATED_ACC) gm = gate[(long long)m * gateStride];
#pragma unroll
        for (int j = 0; j < TN; j += 4) {
            const int n = col0 + tx * TN + j;
            const long long cidx = (long long)m * N + n;
            float r0 = acc[i][j + 0], r1 = acc[i][j + 1];
            float r2 = acc[i][j + 2], r3 = acc[i][j + 3];
            if (EPI == EPI_SCALE) { r0 *= alpha; r1 *= alpha; r2 *= alpha; r3 *= alpha; }
            if (EPI == EPI_BIAS || EPI == EPI_BIAS_RELU ||
                EPI == EPI_BIAS_RESID || EPI == EPI_GATED_ACC) {
                float4 bvv = *(const float4*)&bias[n];
                r0 += bvv.x; r1 += bvv.y; r2 += bvv.z; r3 += bvv.w;
            }
            if (EPI == EPI_BIAS_RELU) {
                r0 = fmaxf(r0, 0.0f); r1 = fmaxf(r1, 0.0f);
                r2 = fmaxf(r2, 0.0f); r3 = fmaxf(r3, 0.0f);
            }
            if (EPI == EPI_BIAS_RESID) {
                float4 rv = *(const float4*)&resid[cidx];
                r0 += rv.x; r1 += rv.y; r2 += rv.z; r3 += rv.w;
            }
            if (EPI == EPI_GATED_ACC) {
                float4 o = *(const float4*)&C[cidx];
                r0 = o.x + gm * r0; r1 = o.y + gm * r1;
                r2 = o.z + gm * r2; r3 = o.w + gm * r3;
            }
            float4 outv = make_float4(r0, r1, r2, r3);
            *(float4*)&C[cidx] = outv;
        }
    }
}

// Row-wise softmax over 1024 columns (in place). One block per row.
__global__ void softmax_rows(float* __restrict__ S, int ncols)
{
    const int row = blockIdx.x;
    float* p = S + (long long)row * ncols;
    const int tid = threadIdx.x;
    __shared__ float red[256];

    float m = -1e30f;
    for (int c = tid; c < ncols; c += 256) m = fmaxf(m, p[c]);
    red[tid] = m; __syncthreads();
    for (int s = 128; s > 0; s >>= 1) {
        if (tid < s) red[tid] = fmaxf(red[tid], red[tid + s]);
        __syncthreads();
    }
    m = red[0];
    __syncthreads();

    float sum = 0.0f;
    for (int c = tid; c < ncols; c += 256) {
        float e = __expf(p[c] - m);
        p[c] = e;
        sum += e;
    }
    red[tid] = sum; __syncthreads();
    for (int s = 128; s > 0; s >>= 1) {
        if (tid < s) red[tid] += red[tid + s];
        __syncthreads();
    }
    const float inv = 1.0f / red[0];
    for (int c = tid; c < ncols; c += 256) p[c] *= inv;
}

// gates = softmax(x2 @ Wg + bg) over E=8. One block (256 thr) per token.
__global__ void gates_kernel(const float* __restrict__ x2,
                             const float* __restrict__ Wg,
                             const float* __restrict__ bg,
                             float* __restrict__ G)
{
    const int row = blockIdx.x;
    const int tid = threadIdx.x;
    const float* xp = x2 + (long long)row * 1024;

    float part[8];
#pragma unroll
    for (int e = 0; e < 8; e++) part[e] = 0.0f;

    for (int h = tid; h < 1024; h += 256) {
        float xv = xp[h];
#pragma unroll
        for (int e = 0; e < 8; e++)
            part[e] = fmaf(xv, Wg[h * 8 + e], part[e]);
    }

    __shared__ float red[256];
    __shared__ float logits[8];
#pragma unroll
    for (int e = 0; e < 8; e++) {
        red[tid] = part[e]; __syncthreads();
        for (int s = 128; s > 0; s >>= 1) {
            if (tid < s) red[tid] += red[tid + s];
            __syncthreads();
        }
        if (tid == 0) logits[e] = red[0] + bg[e];
        __syncthreads();
    }

    if (tid == 0) {
        float m = -1e30f;
#pragma unroll
        for (int e = 0; e < 8; e++) m = fmaxf(m, logits[e]);
        float ex[8], s = 0.0f;
#pragma unroll
        for (int e = 0; e < 8; e++) { ex[e] = __expf(logits[e] - m); s += ex[e]; }
        const float inv = 1.0f / s;
#pragma unroll
        for (int e = 0; e < 8; e++) G[row * 8 + e] = ex[e] * inv;
    }
}

extern "C" void kernel_launch(void* const* d_in, const int* in_sizes, int n_in,
                              void* d_out, int out_size)
{
    const float* x  = (const float*)d_in[0];
    const float* Wq = (const float*)d_in[1];
    const float* bq = (const float*)d_in[2];
    const float* Wk = (const float*)d_in[3];
    const float* bk = (const float*)d_in[4];
    const float* Wv = (const float*)d_in[5];
    const float* bv = (const float*)d_in[6];
    const float* Wo = (const float*)d_in[7];
    const float* bo = (const float*)d_in[8];
    const float* Wg = (const float*)d_in[9];
    const float* bg = (const float*)d_in[10];
    const float* W1 = (const float*)d_in[11];
    const float* b1 = (const float*)d_in[12];
    const float* W2 = (const float*)d_in[13];
    const float* b2 = (const float*)d_in[14];
    float* out = (float*)d_out;

    float *q, *k, *v, *s, *a, *x2, *g, *h;
    cudaGetSymbolAddress((void**)&q,  g_q);
    cudaGetSymbolAddress((void**)&k,  g_k);
    cudaGetSymbolAddress((void**)&v,  g_v);
    cudaGetSymbolAddress((void**)&s,  g_s);
    cudaGetSymbolAddress((void**)&a,  g_a);
    cudaGetSymbolAddress((void**)&x2, g_x2);
    cudaGetSymbolAddress((void**)&g,  g_g);
    cudaGetSymbolAddress((void**)&h,  g_h);

    const int Mtok = 4096, H = 1024, D = 4096, Sq = 1024, Bn = 4, E = 8;
    dim3 blk(256);

    // --- QKV projections: [4096,1024] @ [1024,1024] + bias ---
    dim3 gr1(H / BN, Mtok / BM, 1);
    sgemm<EPI_BIAS, false><<<gr1, blk>>>(x, Wq, q, Mtok, H, H, 0, 0, 0, bq, nullptr, nullptr, 0, 1.0f);
    sgemm<EPI_BIAS, false><<<gr1, blk>>>(x, Wk, k, Mtok, H, H, 0, 0, 0, bk, nullptr, nullptr, 0, 1.0f);
    sgemm<EPI_BIAS, false><<<gr1, blk>>>(x, Wv, v, Mtok, H, H, 0, 0, 0, bv, nullptr, nullptr, 0, 1.0f);

    // --- scores_b = Q_b @ K_b^T * (1/sqrt(H)), batched over B=4 ---
    dim3 gr2(Sq / BN, Sq / BM, Bn);
    sgemm<EPI_SCALE, true><<<gr2, blk>>>(q, k, s, Sq, Sq, H,
                                         (long long)Sq * H, (long long)Sq * H, (long long)Sq * Sq,
                                         nullptr, nullptr, nullptr, 0, 0.03125f);

    // --- softmax over key dim ---
    softmax_rows<<<Bn * Sq, 256>>>(s, Sq);

    // --- a_b = attn_b @ V_b, batched ---
    sgemm<EPI_NONE, false><<<gr2, blk>>>(s, v, a, Sq, H, Sq,
                                         (long long)Sq * Sq, (long long)Sq * H, (long long)Sq * H,
                                         nullptr, nullptr, nullptr, 0, 1.0f);

    // --- output projection + residual: x2 = a @ Wo + bo + x ---
    sgemm<EPI_BIAS_RESID, false><<<gr1, blk>>>(a, Wo, x2, Mtok, H, H, 0, 0, 0, bo, x, nullptr, 0, 1.0f);

    // --- gates = softmax(x2 @ Wg + bg) ---
    gates_kernel<<<Mtok, 256>>>(x2, Wg, bg, g);

    // --- out = x2, then accumulate experts ---
    cudaMemcpyAsync(out, x2, (size_t)Mtok * H * sizeof(float), cudaMemcpyDeviceToDevice, 0);

    dim3 grh(D / BN, Mtok / BM, 1);
    dim3 gro(H / BN, Mtok / BM, 1);
    for (int e = 0; e < E; e++) {
        // h = relu(x2 @ W1_e + b1_e)   [4096,4096]
        sgemm<EPI_BIAS_RELU, false><<<grh, blk>>>(
            x2, W1 + (long long)e * H * D, h, Mtok, D, H, 0, 0, 0,
            b1 + (long long)e * D, nullptr, nullptr, 0, 1.0f);
        // out += gate[:,e] * (h @ W2_e + b2_e)   [4096,1024]
        sgemm<EPI_GATED_ACC, false><<<gro, blk>>>(
            h, W2 + (long long)e * D * H, out, Mtok, H, D, 0, 0, 0,
            b2 + (long long)e * H, nullptr, g + e, E, 1.0f);
    }
}

// round 5
// speedup vs baseline: 2.2053x; 2.2053x over previous
#include <cuda_runtime.h>
#include <cuda_bf16.h>
#include <cstdint>

// ============================================================================
// TinyTransformerBlock on GB300 (compute_103 PTX -> HMMA tensor cores).
// tcgen05 is unavailable at this PTX target; we use mma.sync bf16 (sm_80 ISA)
// which runs on the sm_103a tensor pipe.
// fp32 x ~= hi + lo (bf16 each). GEMM uses A'=[hi,lo,hi], B'=[hi,hi,lo] along
// K' = 3K so dot(A',B') = hi*hi + lo*hi + hi*lo, fp32 accumulated in HMMA.
// Attention core stays fp32 SGEMM.
// ============================================================================

__device__ __forceinline__ uint32_t smem_to_u32(const void* p) {
    uint32_t a;
    asm("{ .reg .u64 t; cvta.to.shared.u64 t, %1; cvt.u32.u64 %0, t; }" : "=r"(a) : "l"(p));
    return a;
}
__device__ __forceinline__ void cp16(uint32_t saddr, const void* g) {
    asm volatile("cp.async.cg.shared.global [%0], [%1], 16;" :: "r"(saddr), "l"(g));
}
#define CP_COMMIT() asm volatile("cp.async.commit_group;" ::: "memory")
#define CP_WAIT_1() asm volatile("cp.async.wait_group 1;" ::: "memory")

__device__ __forceinline__ void ldm_x4(uint32_t* r, uint32_t addr) {
    asm volatile("ldmatrix.sync.aligned.m8n8.x4.shared.b16 {%0,%1,%2,%3}, [%4];"
        : "=r"(r[0]), "=r"(r[1]), "=r"(r[2]), "=r"(r[3]) : "r"(addr));
}
__device__ __forceinline__ void mma_16816(float* c, const uint32_t* a, uint32_t b0, uint32_t b1) {
    asm volatile("mma.sync.aligned.m16n8k16.row.col.f32.bf16.bf16.f32 "
        "{%0,%1,%2,%3}, {%4,%5,%6,%7}, {%8,%9}, {%0,%1,%2,%3};"
        : "+f"(c[0]), "+f"(c[1]), "+f"(c[2]), "+f"(c[3])
        : "r"(a[0]), "r"(a[1]), "r"(a[2]), "r"(a[3]), "r"(b0), "r"(b1));
}

// ---------------- problem sizes ----------------
#define MT 4096            // tokens
#define HH 1024            // hidden
#define DD 4096            // expert dim
#define EE 8               // experts
#define SQ 1024            // seq
#define BB 4               // batch

// ---------------- scratch (device globals; allocation-free) ----------------
__device__ __align__(1024) float g_qkv[3ULL * MT * HH];
__device__ __align__(1024) float g_s[(long long)BB * SQ * SQ];
__device__ __align__(1024) float g_a[(long long)MT * HH];
__device__ __align__(1024) float g_x2[(long long)MT * HH];
__device__ __align__(1024) float g_g[(long long)MT * EE];
__device__ __align__(1024) float g_eout[(long long)EE * MT * HH];
__device__ __align__(1024) __nv_bfloat16 g_xs[(long long)MT * 3 * HH];
__device__ __align__(1024) __nv_bfloat16 g_as[(long long)MT * 3 * HH];
__device__ __align__(1024) __nv_bfloat16 g_x2s[(long long)MT * 3 * HH];
__device__ __align__(1024) __nv_bfloat16 g_wts[4ULL * HH * 3 * HH];          // Wq,Wk,Wv,Wo transposed-split
__device__ __align__(1024) __nv_bfloat16 g_w1ts[(long long)EE * DD * 3 * HH];
__device__ __align__(1024) __nv_bfloat16 g_w2ts[(long long)EE * HH * 3 * DD];
__device__ __align__(1024) __nv_bfloat16 g_hs[(long long)EE * MT * 3 * DD];

struct PtrArr { const float* p[8]; };

__device__ __forceinline__ void split3_pair(float v0, float v1, __nv_bfloat16* base,
                                            long long n, long long K) {
    __nv_bfloat16 h0 = __float2bfloat16_rn(v0), h1 = __float2bfloat16_rn(v1);
    __nv_bfloat16 l0 = __float2bfloat16_rn(v0 - __bfloat162float(h0));
    __nv_bfloat16 l1 = __float2bfloat16_rn(v1 - __bfloat162float(h1));
    __nv_bfloat162 hh; hh.x = h0; hh.y = h1;
    __nv_bfloat162 ll; ll.x = l0; ll.y = l1;
    *(__nv_bfloat162*)&base[n] = hh;           // hi   (A-side ordering: hi, lo, hi)
    *(__nv_bfloat162*)&base[K + n] = ll;       // lo
    *(__nv_bfloat162*)&base[2 * K + n] = hh;   // hi
}

// ---------------- HMMA GEMM: C[M,N] = A'[M,K'] x B'[N,K']^T ----------------
// CTA 128x128, BK=64, 3-stage cp.async pipe, 8 warps (2M x 4N), warp 64x32.
enum { TE_BIAS = 0, TE_BIAS_RESID_SPLIT = 1, TE_BIAS_RELU_SPLIT = 2, TE_STORE = 3 };

#define HG_STAGE 32768          // A 16KB + B 16KB
#define HG_SMEM (3 * HG_STAGE)

// copy one 128x64 bf16 tile (row0-relative rows) into SW128-swizzled smem
__device__ __forceinline__ void load_tile_cp(uint32_t sbase, const __nv_bfloat16* g,
                                             long long ld, int row0, int k0, int tid)
{
    const int r = tid >> 1;
    const int c0 = (tid & 1) * 4;
    const __nv_bfloat16* gp = g + (long long)(row0 + r) * ld + k0 + c0 * 8;
    const uint32_t srow = sbase + r * 128;
#pragma unroll
    for (int i = 0; i < 4; i++)
        cp16(srow + (((c0 + i) ^ (r & 7)) << 4), gp + i * 8);
}

template <int EPI>
__global__ void __launch_bounds__(256)
hmma_gemm(const __nv_bfloat16* __restrict__ A, long long aZ,
          const __nv_bfloat16* __restrict__ B, long long bZ,
          int Kp, float* C, long long cZ, PtrArr bias, const float* resid,
          __nv_bfloat16* split, long long splitZ, int splitK)
{
    extern __shared__ __align__(1024) char smem[];
    const uint32_t sb = smem_to_u32(smem);
    const int tid = threadIdx.x;
    const int wid = tid >> 5, lane = tid & 31;
    const int z = blockIdx.z;
    const int m0 = blockIdx.y << 7;
    const int n0 = blockIdx.x << 7;
    const int Nt = gridDim.x << 7;
    const __nv_bfloat16* Az = A + (long long)z * aZ;
    const __nv_bfloat16* Bz = B + (long long)z * bZ;
    const int nch = Kp >> 6;

    const int wm = (wid >> 2) * 64;     // warp M offset in tile
    const int wn = (wid & 3) * 32;      // warp N offset in tile

    float acc[4][4][4];
#pragma unroll
    for (int i = 0; i < 4; i++)
#pragma unroll
        for (int j = 0; j < 4; j++)
#pragma unroll
            for (int r = 0; r < 4; r++) acc[i][j][r] = 0.0f;

    // prologue: chunks 0,1 -> stages 0,1
    load_tile_cp(sb, Az, Kp, m0, 0, tid);
    load_tile_cp(sb + 16384, Bz, Kp, n0, 0, tid);
    CP_COMMIT();
    load_tile_cp(sb + HG_STAGE, Az, Kp, m0, 64, tid);
    load_tile_cp(sb + HG_STAGE + 16384, Bz, Kp, n0, 64, tid);
    CP_COMMIT();

    // precomputed fragment row indices
    const int arow = lane & 15;           // row within 16-row m-tile
    const int ahalf = lane >> 4;          // k half (0/1)
    const int brow = (lane & 7) + ((lane >> 4) & 1) * 8;   // row within 16-row n-group
    const int bhalf = (lane >> 3) & 1;    // k half

    for (int c = 0; c < nch; c++) {
        CP_WAIT_1();
        __syncthreads();
        // issue chunk c+2 into stage (c+2)%3 (finished at iter c-1)
        if (c + 2 < nch) {
            const uint32_t st = sb + ((c + 2) % 3) * HG_STAGE;
            load_tile_cp(st, Az, Kp, m0, (c + 2) * 64, tid);
            load_tile_cp(st + 16384, Bz, Kp, n0, (c + 2) * 64, tid);
        }
        CP_COMMIT();

        const uint32_t sA = sb + (c % 3) * HG_STAGE;
        const uint32_t sB = sA + 16384;
#pragma unroll
        for (int ks = 0; ks < 4; ks++) {
            uint32_t a[4][4];
#pragma unroll
            for (int mi = 0; mi < 4; mi++) {
                const int row = wm + mi * 16 + arow;
                const int ch = ks * 2 + ahalf;
                ldm_x4(a[mi], sA + row * 128 + ((ch ^ (row & 7)) << 4));
            }
            uint32_t b[2][4];
#pragma unroll
            for (int gI = 0; gI < 2; gI++) {
                const int row = wn + gI * 16 + brow;
                const int ch = ks * 2 + bhalf;
                ldm_x4(b[gI], sB + row * 128 + ((ch ^ (row & 7)) << 4));
            }
#pragma unroll
            for (int mi = 0; mi < 4; mi++)
#pragma unroll
                for (int ni = 0; ni < 4; ni++) {
                    const int gI = ni >> 1, off = (ni & 1) * 2;
                    mma_16816(acc[mi][ni], a[mi], b[gI][off], b[gI][off + 1]);
                }
        }
        __syncthreads();
    }

    // ---- epilogue ----
    const int l4 = lane >> 2, l2 = (lane & 3) << 1;
    float* Cz = C + (long long)z * cZ;
    const float* bz = bias.p[z];
    __nv_bfloat16* spz = (EPI == TE_BIAS_RESID_SPLIT || EPI == TE_BIAS_RELU_SPLIT)
                             ? split + (long long)z * splitZ : nullptr;

#pragma unroll
    for (int mi = 0; mi < 4; mi++)
#pragma unroll
        for (int h = 0; h < 2; h++) {
            const long long m = (long long)m0 + wm + mi * 16 + l4 + h * 8;
#pragma unroll
            for (int ni = 0; ni < 4; ni++) {
                const long long n = n0 + wn + ni * 8 + l2;
                float v0 = acc[mi][ni][h * 2 + 0];
                float v1 = acc[mi][ni][h * 2 + 1];
                if (EPI != TE_STORE) {
                    v0 += bz[n]; v1 += bz[n + 1];
                }
                if (EPI == TE_BIAS_RELU_SPLIT) {
                    v0 = fmaxf(v0, 0.0f); v1 = fmaxf(v1, 0.0f);
                }
                if (EPI == TE_BIAS_RESID_SPLIT) {
                    float2 rv = *(const float2*)&resid[m * Nt + n];
                    v0 += rv.x; v1 += rv.y;
                }
                if (EPI == TE_BIAS || EPI == TE_STORE || EPI == TE_BIAS_RESID_SPLIT) {
                    float2 o; o.x = v0; o.y = v1;
                    *(float2*)&Cz[m * Nt + n] = o;
                }
                if (EPI == TE_BIAS_RESID_SPLIT || EPI == TE_BIAS_RELU_SPLIT) {
                    split3_pair(v0, v1, spz + m * (3LL * splitK), n, splitK);
                }
            }
        }
}

// ---------------- split helpers ----------------
// A-side row split: in [M,K] fp32 -> out [M,3K] bf16 [hi, lo, hi]
__global__ void row_split(const float* __restrict__ in, __nv_bfloat16* __restrict__ out, int K)
{
    const long long i = (long long)blockIdx.x * blockDim.x + threadIdx.x;
    const int K4 = K >> 2;
    const long long mrow = i / K4;
    const int k4 = (int)(i % K4) << 2;
    float4 v = *(const float4*)&in[mrow * K + k4];
    __nv_bfloat16* o = out + mrow * (3LL * K);
    split3_pair(v.x, v.y, o, k4, K);
    split3_pair(v.z, v.w, o, k4 + 2, K);
}

// B-side transpose split: in [K,N] fp32 -> out [N,3K] bf16 [hi, hi, lo]
__global__ void transpose_split(PtrArr in, int K, int N,
                                __nv_bfloat16* __restrict__ out, long long outZ)
{
    __shared__ float t[64][65];
    const float* src = in.p[blockIdx.z];
    __nv_bfloat16* dst = out + blockIdx.z * outZ;
    const int n0 = blockIdx.x * 64, k0 = blockIdx.y * 64;
    const int tr = threadIdx.x >> 6;      // 0..3
    const int tc = threadIdx.x & 63;      // 0..63
#pragma unroll
    for (int j = 0; j < 16; j++) {
        const int r = tr + j * 4;
        t[r][tc] = src[(long long)(k0 + r) * N + n0 + tc];
    }
    __syncthreads();
#pragma unroll
    for (int j = 0; j < 16; j++) {
        const int rn = tr + j * 4;        // local n
        const float v = t[tc][rn];
        const __nv_bfloat16 hi = __float2bfloat16_rn(v);
        const __nv_bfloat16 lo = __float2bfloat16_rn(v - __bfloat162float(hi));
        __nv_bfloat16* o = dst + (long long)(n0 + rn) * (3LL * K) + k0 + tc;
        o[0] = hi;             // hi
        o[K] = hi;             // hi
        o[2LL * K] = lo;       // lo
    }
}

// ---------------- fp32 attention core ----------------
#define BSM 128
#define BSN 128
#define BSK 8

enum { EPI_NONE = 0, EPI_SCALE = 1 };

template <int EPI, bool TRANSB>
__launch_bounds__(256, 2)
__global__ void sgemm(const float* __restrict__ A, const float* __restrict__ B,
                      float* __restrict__ C, int M, int N, int K,
                      long long sA, long long sB, long long sC, float alpha)
{
    __shared__ float As[BSK][BSM];
    __shared__ float Bs[BSK][BSN];
    const int bz = blockIdx.z;
    A += (long long)bz * sA; B += (long long)bz * sB; C += (long long)bz * sC;
    const int row0 = blockIdx.y * BSM, col0 = blockIdx.x * BSN;
    const int tid = threadIdx.x;
    const int tx = tid & 15, ty = tid >> 4;
    const int arow = tid >> 1, acol = (tid & 1) * 4;
    const float* Aptr = A + (long long)(row0 + arow) * K + acol;
    const int bnrow = tid >> 5, bncol = (tid & 31) * 4;
    const int btn = tid >> 1, btk = (tid & 1) * 4;
    const float* Bptr = TRANSB ? B + (long long)(col0 + btn) * K + btk
                               : B + (long long)bnrow * N + col0 + bncol;
    float acc[8][8];
#pragma unroll
    for (int i = 0; i < 8; i++)
#pragma unroll
        for (int j = 0; j < 8; j++) acc[i][j] = 0.0f;

    for (int k0 = 0; k0 < K; k0 += BSK) {
        float4 av = *(const float4*)Aptr;
        As[acol + 0][arow] = av.x; As[acol + 1][arow] = av.y;
        As[acol + 2][arow] = av.z; As[acol + 3][arow] = av.w;
        float4 bv = *(const float4*)Bptr;
        if (TRANSB) {
            Bs[btk + 0][btn] = bv.x; Bs[btk + 1][btn] = bv.y;
            Bs[btk + 2][btn] = bv.z; Bs[btk + 3][btn] = bv.w;
        } else {
            *(float4*)&Bs[bnrow][bncol] = bv;
        }
        __syncthreads();
#pragma unroll
        for (int kk = 0; kk < BSK; kk++) {
            float a[8], b[8];
            *(float4*)&a[0] = *(const float4*)&As[kk][ty * 8];
            *(float4*)&a[4] = *(const float4*)&As[kk][ty * 8 + 4];
            *(float4*)&b[0] = *(const float4*)&Bs[kk][tx * 8];
            *(float4*)&b[4] = *(const float4*)&Bs[kk][tx * 8 + 4];
#pragma unroll
            for (int i = 0; i < 8; i++)
#pragma unroll
                for (int j = 0; j < 8; j++) acc[i][j] = fmaf(a[i], b[j], acc[i][j]);
        }
        __syncthreads();
        Aptr += BSK;
        if (TRANSB) Bptr += BSK; else Bptr += (long long)BSK * N;
    }
#pragma unroll
    for (int i = 0; i < 8; i++) {
        const int m = row0 + ty * 8 + i;
#pragma unroll
        for (int j = 0; j < 8; j += 4) {
            const int n = col0 + tx * 8 + j;
            float r0 = acc[i][j], r1 = acc[i][j + 1], r2 = acc[i][j + 2], r3 = acc[i][j + 3];
            if (EPI == EPI_SCALE) { r0 *= alpha; r1 *= alpha; r2 *= alpha; r3 *= alpha; }
            *(float4*)&C[(long long)m * N + n] = make_float4(r0, r1, r2, r3);
        }
    }
}

__global__ void softmax_rows(float* __restrict__ S, int ncols)
{
    const int row = blockIdx.x;
    float* p = S + (long long)row * ncols;
    const int tid = threadIdx.x;
    __shared__ float red[256];
    float m = -1e30f;
    for (int c = tid; c < ncols; c += 256) m = fmaxf(m, p[c]);
    red[tid] = m; __syncthreads();
    for (int s = 128; s > 0; s >>= 1) { if (tid < s) red[tid] = fmaxf(red[tid], red[tid + s]); __syncthreads(); }
    m = red[0]; __syncthreads();
    float sum = 0.0f;
    for (int c = tid; c < ncols; c += 256) { float e = __expf(p[c] - m); p[c] = e; sum += e; }
    red[tid] = sum; __syncthreads();
    for (int s = 128; s > 0; s >>= 1) { if (tid < s) red[tid] += red[tid + s]; __syncthreads(); }
    const float inv = 1.0f / red[0];
    for (int c = tid; c < ncols; c += 256) p[c] *= inv;
}

__global__ void gates_kernel(const float* __restrict__ x2, const float* __restrict__ Wg,
                             const float* __restrict__ bg, float* __restrict__ G)
{
    const int row = blockIdx.x;
    const int tid = threadIdx.x;
    const float* xp = x2 + (long long)row * HH;
    float part[8];
#pragma unroll
    for (int e = 0; e < 8; e++) part[e] = 0.0f;
    for (int h = tid; h < HH; h += 256) {
        float xv = xp[h];
#pragma unroll
        for (int e = 0; e < 8; e++) part[e] = fmaf(xv, Wg[h * 8 + e], part[e]);
    }
    __shared__ float red[256];
    __shared__ float logits[8];
#pragma unroll
    for (int e = 0; e < 8; e++) {
        red[tid] = part[e]; __syncthreads();
        for (int s = 128; s > 0; s >>= 1) { if (tid < s) red[tid] += red[tid + s]; __syncthreads(); }
        if (tid == 0) logits[e] = red[0] + bg[e];
        __syncthreads();
    }
    if (tid == 0) {
        float m = -1e30f;
#pragma unroll
        for (int e = 0; e < 8; e++) m = fmaxf(m, logits[e]);
        float ex[8], s = 0.0f;
#pragma unroll
        for (int e = 0; e < 8; e++) { ex[e] = __expf(logits[e] - m); s += ex[e]; }
        const float inv = 1.0f / s;
#pragma unroll
        for (int e = 0; e < 8; e++) G[row * 8 + e] = ex[e] * inv;
    }
}

// out[m,n] = x2[m,n] + sum_e g[m,e] * (eout[e][m,n] + b2[e][n])
__global__ void moe_reduce(const float* __restrict__ x2, const float* __restrict__ eout,
                           const float* __restrict__ g, const float* __restrict__ b2,
                           float* __restrict__ out)
{
    const long long i = (long long)blockIdx.x * blockDim.x + threadIdx.x;
    const long long m = i / (HH / 4);
    const int n4 = (int)(i % (HH / 4)) << 2;
    float4 acc = *(const float4*)&x2[m * HH + n4];
#pragma unroll
    for (int e = 0; e < 8; e++) {
        const float ge = g[m * 8 + e];
        float4 eo = *(const float4*)&eout[((long long)e * MT + m) * HH + n4];
        float4 b = *(const float4*)&b2[e * HH + n4];
        acc.x += ge * (eo.x + b.x); acc.y += ge * (eo.y + b.y);
        acc.z += ge * (eo.z + b.z); acc.w += ge * (eo.w + b.w);
    }
    *(float4*)&out[m * HH + n4] = acc;
}

// ---------------- host side ----------------
extern "C" void kernel_launch(void* const* d_in, const int* in_sizes, int n_in,
                              void* d_out, int out_size)
{
    const float* x  = (const float*)d_in[0];
    const float* Wq = (const float*)d_in[1];
    const float* bq = (const float*)d_in[2];
    const float* Wk = (const float*)d_in[3];
    const float* bk = (const float*)d_in[4];
    const float* Wv = (const float*)d_in[5];
    const float* bv = (const float*)d_in[6];
    const float* Wo = (const float*)d_in[7];
    const float* bo = (const float*)d_in[8];
    const float* Wg = (const float*)d_in[9];
    const float* bg = (const float*)d_in[10];
    const float* W1 = (const float*)d_in[11];
    const float* b1 = (const float*)d_in[12];
    const float* W2 = (const float*)d_in[13];
    const float* b2 = (const float*)d_in[14];
    float* out = (float*)d_out;

    float *qkv, *s, *a, *x2, *g, *eout;
    __nv_bfloat16 *xs, *as, *x2s, *wts, *w1ts, *w2ts, *hs;
    cudaGetSymbolAddress((void**)&qkv, g_qkv);
    cudaGetSymbolAddress((void**)&s, g_s);
    cudaGetSymbolAddress((void**)&a, g_a);
    cudaGetSymbolAddress((void**)&x2, g_x2);
    cudaGetSymbolAddress((void**)&g, g_g);
    cudaGetSymbolAddress((void**)&eout, g_eout);
    cudaGetSymbolAddress((void**)&xs, g_xs);
    cudaGetSymbolAddress((void**)&as, g_as);
    cudaGetSymbolAddress((void**)&x2s, g_x2s);
    cudaGetSymbolAddress((void**)&wts, g_wts);
    cudaGetSymbolAddress((void**)&w1ts, g_w1ts);
    cudaGetSymbolAddress((void**)&w2ts, g_w2ts);
    cudaGetSymbolAddress((void**)&hs, g_hs);

    cudaFuncSetAttribute(hmma_gemm<TE_BIAS>, cudaFuncAttributeMaxDynamicSharedMemorySize, HG_SMEM);
    cudaFuncSetAttribute(hmma_gemm<TE_BIAS_RESID_SPLIT>, cudaFuncAttributeMaxDynamicSharedMemorySize, HG_SMEM);
    cudaFuncSetAttribute(hmma_gemm<TE_BIAS_RELU_SPLIT>, cudaFuncAttributeMaxDynamicSharedMemorySize, HG_SMEM);
    cudaFuncSetAttribute(hmma_gemm<TE_STORE>, cudaFuncAttributeMaxDynamicSharedMemorySize, HG_SMEM);

    PtrArr bnone = {};
    dim3 blk(256);

    // 1. splits of inputs / weights
    row_split<<<(MT * HH / 4) / 256, blk>>>(x, xs, HH);
    {
        PtrArr wi; wi.p[0] = Wq; wi.p[1] = Wk; wi.p[2] = Wv; wi.p[3] = Wo;
        transpose_split<<<dim3(HH / 64, HH / 64, 4), blk>>>(wi, HH, HH, wts, 3LL * HH * HH);
    }
    {
        PtrArr wi;
        for (int e = 0; e < 8; e++) wi.p[e] = W1 + (long long)e * HH * DD;
        transpose_split<<<dim3(DD / 64, HH / 64, EE), blk>>>(wi, HH, DD, w1ts, 3LL * HH * DD);
    }
    {
        PtrArr wi;
        for (int e = 0; e < 8; e++) wi.p[e] = W2 + (long long)e * DD * HH;
        transpose_split<<<dim3(HH / 64, DD / 64, EE), blk>>>(wi, DD, HH, w2ts, 3LL * DD * HH);
    }

    // 2. QKV projections (batched z=3): qkv_z = xs @ wts_z^T + b_z
    {
        PtrArr ba; ba.p[0] = bq; ba.p[1] = bk; ba.p[2] = bv;
        hmma_gemm<TE_BIAS><<<dim3(HH / 128, MT / 128, 3), blk, HG_SMEM>>>(
            xs, 0, wts, 3LL * HH * HH, 3 * HH, qkv, (long long)MT * HH, ba,
            nullptr, nullptr, 0, 0);
    }
    const float* q = qkv;
    const float* kk2 = qkv + (long long)MT * HH;
    const float* v = qkv + 2LL * MT * HH;

    // 3. attention core (fp32)
    sgemm<EPI_SCALE, true><<<dim3(SQ / BSN, SQ / BSM, BB), blk>>>(
        q, kk2, s, SQ, SQ, HH, (long long)SQ * HH, (long long)SQ * HH, (long long)SQ * SQ, 0.03125f);
    softmax_rows<<<BB * SQ, 256>>>(s, SQ);
    sgemm<EPI_NONE, false><<<dim3(HH / BSN, SQ / BSM, BB), blk>>>(
        s, v, a, SQ, HH, SQ, (long long)SQ * SQ, (long long)SQ * HH, (long long)SQ * HH, 1.0f);

    // 4. O projection + residual -> x2 (fp32) and x2s (split)
    row_split<<<(MT * HH / 4) / 256, blk>>>(a, as, HH);
    {
        PtrArr ba; ba.p[0] = bo;
        hmma_gemm<TE_BIAS_RESID_SPLIT><<<dim3(HH / 128, MT / 128, 1), blk, HG_SMEM>>>(
            as, 0, wts + 3ULL * HH * HH * 3, 0, 3 * HH, x2, 0, ba, x, x2s, 0, HH);
    }

    // 5. gates
    gates_kernel<<<MT, 256>>>(x2, Wg, bg, g);

    // 6. expert up-proj (batched z=8): hs_e = split(relu(x2s @ w1ts_e^T + b1_e))
    {
        PtrArr ba;
        for (int e = 0; e < 8; e++) ba.p[e] = b1 + (long long)e * DD;
        hmma_gemm<TE_BIAS_RELU_SPLIT><<<dim3(DD / 128, MT / 128, EE), blk, HG_SMEM>>>(
            x2s, 0, w1ts, 3LL * HH * DD, 3 * HH, nullptr, 0, ba, nullptr,
            hs, 3LL * MT * DD, DD);
    }

    // 7. expert down-proj (batched z=8): eout_e = hs_e @ w2ts_e^T
    hmma_gemm<TE_STORE><<<dim3(HH / 128, MT / 128, EE), blk, HG_SMEM>>>(
        hs, 3LL * MT * DD, w2ts, 3LL * DD * HH, 3 * DD, eout, (long long)MT * HH, bnone,
        nullptr, nullptr, 0, 0);

    // 8. final reduce: out = x2 + sum_e g_e * (eout_e + b2_e)
    moe_reduce<<<(MT * HH / 4) / 256, blk>>>(x2, eout, g, b2, out);
}

// round 7
// speedup vs baseline: 3.0778x; 1.3956x over previous
#include <cuda_runtime.h>
#include <cuda_bf16.h>
#include <cuda_fp16.h>
#include <cstdint>

// ============================================================================
// TinyTransformerBlock on GB300 (compute_103 PTX -> HMMA fp16 tensor cores).
// fp32 x ~= hi + lo (fp16 each).
//  - QKV/O projections: 3-term split  A'=[hi,lo,hi] x B'=[hi,hi,lo], K'=3K
//    (error ~2^-22, negligible)
//  - MoE up/down:       2-term split  A'=[hi,lo]    x B'=[hi,hi],    K'=2K
//    (computes A * hi(W); dropped A*lo(W) ~ 2.8e-4 norm-relative)
// fp32 accumulation in HMMA. Attention core stays fp32 SGEMM.
// ============================================================================

__device__ __forceinline__ uint32_t smem_to_u32(const void* p) {
    uint32_t a;
    asm("{ .reg .u64 t; cvta.to.shared.u64 t, %1; cvt.u32.u64 %0, t; }" : "=r"(a) : "l"(p));
    return a;
}
__device__ __forceinline__ void cp16(uint32_t saddr, const void* g) {
    asm volatile("cp.async.cg.shared.global [%0], [%1], 16;" :: "r"(saddr), "l"(g));
}
#define CP_COMMIT() asm volatile("cp.async.commit_group;" ::: "memory")
#define CP_WAIT_1() asm volatile("cp.async.wait_group 1;" ::: "memory")

__device__ __forceinline__ void ldm_x4(uint32_t* r, uint32_t addr) {
    asm volatile("ldmatrix.sync.aligned.m8n8.x4.shared.b16 {%0,%1,%2,%3}, [%4];"
        : "=r"(r[0]), "=r"(r[1]), "=r"(r[2]), "=r"(r[3]) : "r"(addr));
}
__device__ __forceinline__ void mma_16816(float* c, const uint32_t* a, uint32_t b0, uint32_t b1) {
    asm volatile("mma.sync.aligned.m16n8k16.row.col.f32.f16.f16.f32 "
        "{%0,%1,%2,%3}, {%4,%5,%6,%7}, {%8,%9}, {%0,%1,%2,%3};"
        : "+f"(c[0]), "+f"(c[1]), "+f"(c[2]), "+f"(c[3])
        : "r"(a[0]), "r"(a[1]), "r"(a[2]), "r"(a[3]), "r"(b0), "r"(b1));
}

// ---------------- problem sizes ----------------
#define MT 4096            // tokens
#define HH 1024            // hidden
#define DD 4096            // expert dim
#define EE 8               // experts
#define SQ 1024            // seq
#define BB 4               // batch

// ---------------- scratch (device globals; allocation-free) ----------------
__device__ __align__(1024) float g_qkv[3ULL * MT * HH];
__device__ __align__(1024) float g_s[(long long)BB * SQ * SQ];
__device__ __align__(1024) float g_a[(long long)MT * HH];
__device__ __align__(1024) float g_x2[(long long)MT * HH];
__device__ __align__(1024) float g_g[(long long)MT * EE];
__device__ __align__(1024) float g_eout[(long long)EE * MT * HH];
__device__ __align__(1024) __half g_xs[(long long)MT * 3 * HH];              // 3-term A
__device__ __align__(1024) __half g_as[(long long)MT * 3 * HH];              // 3-term A
__device__ __align__(1024) __half g_x2s[(long long)MT * 2 * HH];             // 2-term A
__device__ __align__(1024) __half g_wts[4ULL * HH * 3 * HH];                 // Wq,Wk,Wv,Wo 3-term B
__device__ __align__(1024) __half g_w1ts[(long long)EE * DD * 2 * HH];       // 2-term B
__device__ __align__(1024) __half g_w2ts[(long long)EE * HH * 2 * DD];       // 2-term B
__device__ __align__(1024) __half g_hs[(long long)EE * MT * 2 * DD];         // 2-term A

struct PtrArr { const float* p[8]; };

// A-side 3-term: [hi, lo, hi]
__device__ __forceinline__ void split3_pairA(float v0, float v1, __half* base,
                                             long long n, long long K) {
    __half h0 = __float2half_rn(v0), h1 = __float2half_rn(v1);
    __half l0 = __float2half_rn(v0 - __half2float(h0));
    __half l1 = __float2half_rn(v1 - __half2float(h1));
    __half2 hh = __halves2half2(h0, h1);
    __half2 ll = __halves2half2(l0, l1);
    *(__half2*)&base[n] = hh;
    *(__half2*)&base[K + n] = ll;
    *(__half2*)&base[2 * K + n] = hh;
}
// A-side 2-term: [hi, lo]
__device__ __forceinline__ void split2_pairA(float v0, float v1, __half* base,
                                             long long n, long long K) {
    __half h0 = __float2half_rn(v0), h1 = __float2half_rn(v1);
    __half l0 = __float2half_rn(v0 - __half2float(h0));
    __half l1 = __float2half_rn(v1 - __half2float(h1));
    *(__half2*)&base[n] = __halves2half2(h0, h1);
    *(__half2*)&base[K + n] = __halves2half2(l0, l1);
}

// ---------------- HMMA GEMM: C[M,N] = A'[M,K'] x B'[N,K']^T ----------------
// CTA 128x128, BK=64, 3-stage cp.async pipe, 8 warps (2M x 4N), warp 64x32.
enum { TE_BIAS = 0, TE_BIAS_RESID_SPLIT2 = 1, TE_BIAS_RELU_SPLIT2 = 2, TE_STORE = 3 };

#define HG_STAGE 32768          // A 16KB + B 16KB
#define HG_SMEM (3 * HG_STAGE)

// copy one 128x64 fp16 tile (row0-relative rows) into swizzled smem
__device__ __forceinline__ void load_tile_cp(uint32_t sbase, const __half* g,
                                             long long ld, int row0, int k0, int tid)
{
    const int r = tid >> 1;
    const int c0 = (tid & 1) * 4;
    const __half* gp = g + (long long)(row0 + r) * ld + k0 + c0 * 8;
    const uint32_t srow = sbase + r * 128;
#pragma unroll
    for (int i = 0; i < 4; i++)
        cp16(srow + (((c0 + i) ^ (r & 7)) << 4), gp + i * 8);
}

template <int EPI>
__global__ void __launch_bounds__(256)
hmma_gemm(const __half* __restrict__ A, long long aZ,
          const __half* __restrict__ B, long long bZ,
          int Kp, float* C, long long cZ, PtrArr bias, const float* resid,
          __half* split, long long splitZ, int splitK)
{
    extern __shared__ __align__(1024) char smem[];
    const uint32_t sb = smem_to_u32(smem);
    const int tid = threadIdx.x;
    const int wid = tid >> 5, lane = tid & 31;
    const int z = blockIdx.z;
    const int m0 = blockIdx.y << 7;
    const int n0 = blockIdx.x << 7;
    const int Nt = gridDim.x << 7;
    const __half* Az = A + (long long)z * aZ;
    const __half* Bz = B + (long long)z * bZ;
    const int nch = Kp >> 6;

    const int wm = (wid >> 2) * 64;     // warp M offset in tile
    const int wn = (wid & 3) * 32;      // warp N offset in tile

    float acc[4][4][4];
#pragma unroll
    for (int i = 0; i < 4; i++)
#pragma unroll
        for (int j = 0; j < 4; j++)
#pragma unroll
            for (int r = 0; r < 4; r++) acc[i][j][r] = 0.0f;

    // prologue: chunks 0,1 -> stages 0,1
    load_tile_cp(sb, Az, Kp, m0, 0, tid);
    load_tile_cp(sb + 16384, Bz, Kp, n0, 0, tid);
    CP_COMMIT();
    load_tile_cp(sb + HG_STAGE, Az, Kp, m0, 64, tid);
    load_tile_cp(sb + HG_STAGE + 16384, Bz, Kp, n0, 64, tid);
    CP_COMMIT();

    // fragment row indices
    const int arow = lane & 15;
    const int ahalf = lane >> 4;
    const int brow = (lane & 7) + ((lane >> 4) & 1) * 8;
    const int bhalf = (lane >> 3) & 1;

    for (int c = 0; c < nch; c++) {
        CP_WAIT_1();
        __syncthreads();
        if (c + 2 < nch) {
            const uint32_t st = sb + ((c + 2) % 3) * HG_STAGE;
            load_tile_cp(st, Az, Kp, m0, (c + 2) * 64, tid);
            load_tile_cp(st + 16384, Bz, Kp, n0, (c + 2) * 64, tid);
        }
        CP_COMMIT();

        const uint32_t sA = sb + (c % 3) * HG_STAGE;
        const uint32_t sB = sA + 16384;
#pragma unroll
        for (int ks = 0; ks < 4; ks++) {
            uint32_t a[4][4];
#pragma unroll
            for (int mi = 0; mi < 4; mi++) {
                const int row = wm + mi * 16 + arow;
                const int ch = ks * 2 + ahalf;
                ldm_x4(a[mi], sA + row * 128 + ((ch ^ (row & 7)) << 4));
            }
            uint32_t b[2][4];
#pragma unroll
            for (int gI = 0; gI < 2; gI++) {
                const int row = wn + gI * 16 + brow;
                const int ch = ks * 2 + bhalf;
                ldm_x4(b[gI], sB + row * 128 + ((ch ^ (row & 7)) << 4));
            }
#pragma unroll
            for (int mi = 0; mi < 4; mi++)
#pragma unroll
                for (int ni = 0; ni < 4; ni++) {
                    const int gI = ni >> 1, off = (ni & 1) * 2;
                    mma_16816(acc[mi][ni], a[mi], b[gI][off], b[gI][off + 1]);
                }
        }
        __syncthreads();
    }

    // ---- epilogue ----
    const int l4 = lane >> 2, l2 = (lane & 3) << 1;
    float* Cz = C + (long long)z * cZ;
    const float* bz = bias.p[z];
    __half* spz = (EPI == TE_BIAS_RESID_SPLIT2 || EPI == TE_BIAS_RELU_SPLIT2)
                      ? split + (long long)z * splitZ : nullptr;

#pragma unroll
    for (int mi = 0; mi < 4; mi++)
#pragma unroll
        for (int h = 0; h < 2; h++) {
            const long long m = (long long)m0 + wm + mi * 16 + l4 + h * 8;
#pragma unroll
            for (int ni = 0; ni < 4; ni++) {
                const long long n = n0 + wn + ni * 8 + l2;
                float v0 = acc[mi][ni][h * 2 + 0];
                float v1 = acc[mi][ni][h * 2 + 1];
                if (EPI != TE_STORE) {
                    v0 += bz[n]; v1 += bz[n + 1];
                }
                if (EPI == TE_BIAS_RELU_SPLIT2) {
                    v0 = fmaxf(v0, 0.0f); v1 = fmaxf(v1, 0.0f);
                }
                if (EPI == TE_BIAS_RESID_SPLIT2) {
                    float2 rv = *(const float2*)&resid[m * Nt + n];
                    v0 += rv.x; v1 += rv.y;
                }
                if (EPI == TE_BIAS || EPI == TE_STORE || EPI == TE_BIAS_RESID_SPLIT2) {
                    float2 o; o.x = v0; o.y = v1;
                    *(float2*)&Cz[m * Nt + n] = o;
                }
                if (EPI == TE_BIAS_RESID_SPLIT2 || EPI == TE_BIAS_RELU_SPLIT2) {
                    split2_pairA(v0, v1, spz + m * (2LL * splitK), n, splitK);
                }
            }
        }
}

// ---------------- split helpers ----------------
// A-side 3-term row split: in [M,K] fp32 -> out [M,3K] fp16 [hi, lo, hi]
__global__ void row_split3(const float* __restrict__ in, __half* __restrict__ out, int K)
{
    const long long i = (long long)blockIdx.x * blockDim.x + threadIdx.x;
    const int K4 = K >> 2;
    const long long mrow = i / K4;
    const int k4 = (int)(i % K4) << 2;
    float4 v = *(const float4*)&in[mrow * K + k4];
    __half* o = out + mrow * (3LL * K);
    split3_pairA(v.x, v.y, o, k4, K);
    split3_pairA(v.z, v.w, o, k4 + 2, K);
}

// B-side transpose split: in [K,N] fp32 -> out [N, TERMS*K] fp16
// TERMS==3: [hi, hi, lo]; TERMS==2: [hi, hi]
template <int TERMS>
__global__ void transpose_split(PtrArr in, int K, int N,
                                __half* __restrict__ out, long long outZ)
{
    __shared__ float t[64][65];
    const float* src = in.p[blockIdx.z];
    __half* dst = out + blockIdx.z * outZ;
    const int n0 = blockIdx.x * 64, k0 = blockIdx.y * 64;
    const int tr = threadIdx.x >> 6;      // 0..3
    const int tc = threadIdx.x & 63;      // 0..63
#pragma unroll
    for (int j = 0; j < 16; j++) {
        const int r = tr + j * 4;
        t[r][tc] = src[(long long)(k0 + r) * N + n0 + tc];
    }
    __syncthreads();
#pragma unroll
    for (int j = 0; j < 16; j++) {
        const int rn = tr + j * 4;        // local n
        const float v = t[tc][rn];
        const __half hi = __float2half_rn(v);
        __half* o = dst + (long long)(n0 + rn) * ((long long)TERMS * K) + k0 + tc;
        o[0] = hi;
        o[K] = hi;
        if (TERMS == 3) {
            o[2LL * K] = __float2half_rn(v - __half2float(hi));
        }
    }
}

// ---------------- fp32 attention core ----------------
#define BSM 128
#define BSN 128
#define BSK 8

enum { EPI_NONE = 0, EPI_SCALE = 1 };

template <int EPI, bool TRANSB>
__launch_bounds__(256, 2)
__global__ void sgemm(const float* __restrict__ A, const float* __restrict__ B,
                      float* __restrict__ C, int M, int N, int K,
                      long long sA, long long sB, long long sC, float alpha)
{
    __shared__ float As[BSK][BSM];
    __shared__ float Bs[BSK][BSN];
    const int bz = blockIdx.z;
    A += (long long)bz * sA; B += (long long)bz * sB; C += (long long)bz * sC;
    const int row0 = blockIdx.y * BSM, col0 = blockIdx.x * BSN;
    const int tid = threadIdx.x;
    const int tx = tid & 15, ty = tid >> 4;
    const int arow = tid >> 1, acol = (tid & 1) * 4;
    const float* Aptr = A + (long long)(row0 + arow) * K + acol;
    const int bnrow = tid >> 5, bncol = (tid & 31) * 4;
    const int btn = tid >> 1, btk = (tid & 1) * 4;
    const float* Bptr = TRANSB ? B + (long long)(col0 + btn) * K + btk
                               : B + (long long)bnrow * N + col0 + bncol;
    float acc[8][8];
#pragma unroll
    for (int i = 0; i < 8; i++)
#pragma unroll
        for (int j = 0; j < 8; j++) acc[i][j] = 0.0f;

    for (int k0 = 0; k0 < K; k0 += BSK) {
        float4 av = *(const float4*)Aptr;
        As[acol + 0][arow] = av.x; As[acol + 1][arow] = av.y;
        As[acol + 2][arow] = av.z; As[acol + 3][arow] = av.w;
        float4 bv = *(const float4*)Bptr;
        if (TRANSB) {
            Bs[btk + 0][btn] = bv.x; Bs[btk + 1][btn] = bv.y;
            Bs[btk + 2][btn] = bv.z; Bs[btk + 3][btn] = bv.w;
        } else {
            *(float4*)&Bs[bnrow][bncol] = bv;
        }
        __syncthreads();
#pragma unroll
        for (int kk = 0; kk < BSK; kk++) {
            float a[8], b[8];
            *(float4*)&a[0] = *(const float4*)&As[kk][ty * 8];
            *(float4*)&a[4] = *(const float4*)&As[kk][ty * 8 + 4];
            *(float4*)&b[0] = *(const float4*)&Bs[kk][tx * 8];
            *(float4*)&b[4] = *(const float4*)&Bs[kk][tx * 8 + 4];
#pragma unroll
            for (int i = 0; i < 8; i++)
#pragma unroll
                for (int j = 0; j < 8; j++) acc[i][j] = fmaf(a[i], b[j], acc[i][j]);
        }
        __syncthreads();
        Aptr += BSK;
        if (TRANSB) Bptr += BSK; else Bptr += (long long)BSK * N;
    }
#pragma unroll
    for (int i = 0; i < 8; i++) {
        const int m = row0 + ty * 8 + i;
#pragma unroll
        for (int j = 0; j < 8; j += 4) {
            const int n = col0 + tx * 8 + j;
            float r0 = acc[i][j], r1 = acc[i][j + 1], r2 = acc[i][j + 2], r3 = acc[i][j + 3];
            if (EPI == EPI_SCALE) { r0 *= alpha; r1 *= alpha; r2 *= alpha; r3 *= alpha; }
            *(float4*)&C[(long long)m * N + n] = make_float4(r0, r1, r2, r3);
        }
    }
}

__global__ void softmax_rows(float* __restrict__ S, int ncols)
{
    const int row = blockIdx.x;
    float* p = S + (long long)row * ncols;
    const int tid = threadIdx.x;
    __shared__ float red[256];
    float m = -1e30f;
    for (int c = tid; c < ncols; c += 256) m = fmaxf(m, p[c]);
    red[tid] = m; __syncthreads();
    for (int s = 128; s > 0; s >>= 1) { if (tid < s) red[tid] = fmaxf(red[tid], red[tid + s]); __syncthreads(); }
    m = red[0]; __syncthreads();
    float sum = 0.0f;
    for (int c = tid; c < ncols; c += 256) { float e = __expf(p[c] - m); p[c] = e; sum += e; }
    red[tid] = sum; __syncthreads();
    for (int s = 128; s > 0; s >>= 1) { if (tid < s) red[tid] += red[tid + s]; __syncthreads(); }
    const float inv = 1.0f / red[0];
    for (int c = tid; c < ncols; c += 256) p[c] *= inv;
}

__global__ void gates_kernel(const float* __restrict__ x2, const float* __restrict__ Wg,
                             const float* __restrict__ bg, float* __restrict__ G)
{
    const int row = blockIdx.x;
    const int tid = threadIdx.x;
    const float* xp = x2 + (long long)row * HH;
    float part[8];
#pragma unroll
    for (int e = 0; e < 8; e++) part[e] = 0.0f;
    for (int h = tid; h < HH; h += 256) {
        float xv = xp[h];
#pragma unroll
        for (int e = 0; e < 8; e++) part[e] = fmaf(xv, Wg[h * 8 + e], part[e]);
    }
    __shared__ float red[256];
    __shared__ float logits[8];
#pragma unroll
    for (int e = 0; e < 8; e++) {
        red[tid] = part[e]; __syncthreads();
        for (int s = 128; s > 0; s >>= 1) { if (tid < s) red[tid] += red[tid + s]; __syncthreads(); }
        if (tid == 0) logits[e] = red[0] + bg[e];
        __syncthreads();
    }
    if (tid == 0) {
        float m = -1e30f;
#pragma unroll
        for (int e = 0; e < 8; e++) m = fmaxf(m, logits[e]);
        float ex[8], s = 0.0f;
#pragma unroll
        for (int e = 0; e < 8; e++) { ex[e] = __expf(logits[e] - m); s += ex[e]; }
        const float inv = 1.0f / s;
#pragma unroll
        for (int e = 0; e < 8; e++) G[row * 8 + e] = ex[e] * inv;
    }
}

// out[m,n] = x2[m,n] + sum_e g[m,e] * (eout[e][m,n] + b2[e][n])
__global__ void moe_reduce(const float* __restrict__ x2, const float* __restrict__ eout,
                           const float* __restrict__ g, const float* __restrict__ b2,
                           float* __restrict__ out)
{
    const long long i = (long long)blockIdx.x * blockDim.x + threadIdx.x;
    const long long m = i / (HH / 4);
    const int n4 = (int)(i % (HH / 4)) << 2;
    float4 acc = *(const float4*)&x2[m * HH + n4];
#pragma unroll
    for (int e = 0; e < 8; e++) {
        const float ge = g[m * 8 + e];
        float4 eo = *(const float4*)&eout[((long long)e * MT + m) * HH + n4];
        float4 b = *(const float4*)&b2[e * HH + n4];
        acc.x += ge * (eo.x + b.x); acc.y += ge * (eo.y + b.y);
        acc.z += ge * (eo.z + b.z); acc.w += ge * (eo.w + b.w);
    }
    *(float4*)&out[m * HH + n4] = acc;
}

// ---------------- host side ----------------
extern "C" void kernel_launch(void* const* d_in, const int* in_sizes, int n_in,
                              void* d_out, int out_size)
{
    const float* x  = (const float*)d_in[0];
    const float* Wq = (const float*)d_in[1];
    const float* bq = (const float*)d_in[2];
    const float* Wk = (const float*)d_in[3];
    const float* bk = (const float*)d_in[4];
    const float* Wv = (const float*)d_in[5];
    const float* bv = (const float*)d_in[6];
    const float* Wo = (const float*)d_in[7];
    const float* bo = (const float*)d_in[8];
    const float* Wg = (const float*)d_in[9];
    const float* bg = (const float*)d_in[10];
    const float* W1 = (const float*)d_in[11];
    const float* b1 = (const float*)d_in[12];
    const float* W2 = (const float*)d_in[13];
    const float* b2 = (const float*)d_in[14];
    float* out = (float*)d_out;

    float *qkv, *s, *a, *x2, *g, *eout;
    __half *xs, *as, *x2s, *wts, *w1ts, *w2ts, *hs;
    cudaGetSymbolAddress((void**)&qkv, g_qkv);
    cudaGetSymbolAddress((void**)&s, g_s);
    cudaGetSymbolAddress((void**)&a, g_a);
    cudaGetSymbolAddress((void**)&x2, g_x2);
    cudaGetSymbolAddress((void**)&g, g_g);
    cudaGetSymbolAddress((void**)&eout, g_eout);
    cudaGetSymbolAddress((void**)&xs, g_xs);
    cudaGetSymbolAddress((void**)&as, g_as);
    cudaGetSymbolAddress((void**)&x2s, g_x2s);
    cudaGetSymbolAddress((void**)&wts, g_wts);
    cudaGetSymbolAddress((void**)&w1ts, g_w1ts);
    cudaGetSymbolAddress((void**)&w2ts, g_w2ts);
    cudaGetSymbolAddress((void**)&hs, g_hs);

    cudaFuncSetAttribute(hmma_gemm<TE_BIAS>, cudaFuncAttributeMaxDynamicSharedMemorySize, HG_SMEM);
    cudaFuncSetAttribute(hmma_gemm<TE_BIAS_RESID_SPLIT2>, cudaFuncAttributeMaxDynamicSharedMemorySize, HG_SMEM);
    cudaFuncSetAttribute(hmma_gemm<TE_BIAS_RELU_SPLIT2>, cudaFuncAttributeMaxDynamicSharedMemorySize, HG_SMEM);
    cudaFuncSetAttribute(hmma_gemm<TE_STORE>, cudaFuncAttributeMaxDynamicSharedMemorySize, HG_SMEM);

    PtrArr bnone = {};
    dim3 blk(256);

    // 1. splits of inputs / weights
    row_split3<<<(MT * HH / 4) / 256, blk>>>(x, xs, HH);
    {
        PtrArr wi; wi.p[0] = Wq; wi.p[1] = Wk; wi.p[2] = Wv; wi.p[3] = Wo;
        transpose_split<3><<<dim3(HH / 64, HH / 64, 4), blk>>>(wi, HH, HH, wts, 3LL * HH * HH);
    }
    {
        PtrArr wi;
        for (int e = 0; e < 8; e++) wi.p[e] = W1 + (long long)e * HH * DD;
        transpose_split<2><<<dim3(DD / 64, HH / 64, EE), blk>>>(wi, HH, DD, w1ts, 2LL * HH * DD);
    }
    {
        PtrArr wi;
        for (int e = 0; e < 8; e++) wi.p[e] = W2 + (long long)e * DD * HH;
        transpose_split<2><<<dim3(HH / 64, DD / 64, EE), blk>>>(wi, DD, HH, w2ts, 2LL * DD * HH);
    }

    // 2. QKV projections (batched z=3, 3-term): qkv_z = xs @ wts_z^T + b_z
    {
        PtrArr ba; ba.p[0] = bq; ba.p[1] = bk; ba.p[2] = bv;
        hmma_gemm<TE_BIAS><<<dim3(HH / 128, MT / 128, 3), blk, HG_SMEM>>>(
            xs, 0, wts, 3LL * HH * HH, 3 * HH, qkv, (long long)MT * HH, ba,
            nullptr, nullptr, 0, 0);
    }
    const float* q = qkv;
    const float* kk2 = qkv + (long long)MT * HH;
    const float* v = qkv + 2LL * MT * HH;

    // 3. attention core (fp32)
    sgemm<EPI_SCALE, true><<<dim3(SQ / BSN, SQ / BSM, BB), blk>>>(
        q, kk2, s, SQ, SQ, HH, (long long)SQ * HH, (long long)SQ * HH, (long long)SQ * SQ, 0.03125f);
    softmax_rows<<<BB * SQ, 256>>>(s, SQ);
    sgemm<EPI_NONE, false><<<dim3(HH / BSN, SQ / BSM, BB), blk>>>(
        s, v, a, SQ, HH, SQ, (long long)SQ * SQ, (long long)SQ * HH, (long long)SQ * HH, 1.0f);

    // 4. O projection + residual -> x2 (fp32) and x2s (2-term split)
    row_split3<<<(MT * HH / 4) / 256, blk>>>(a, as, HH);
    {
        PtrArr ba; ba.p[0] = bo;
        hmma_gemm<TE_BIAS_RESID_SPLIT2><<<dim3(HH / 128, MT / 128, 1), blk, HG_SMEM>>>(
            as, 0, wts + 3ULL * HH * HH * 3, 0, 3 * HH, x2, 0, ba, x, x2s, 0, HH);
    }

    // 5. gates
    gates_kernel<<<MT, 256>>>(x2, Wg, bg, g);

    // 6. expert up-proj (batched z=8, 2-term): hs_e = split2(relu(x2s @ w1ts_e^T + b1_e))
    {
        PtrArr ba;
        for (int e = 0; e < 8; e++) ba.p[e] = b1 + (long long)e * DD;
        hmma_gemm<TE_BIAS_RELU_SPLIT2><<<dim3(DD / 128, MT / 128, EE), blk, HG_SMEM>>>(
            x2s, 0, w1ts, 2LL * HH * DD, 2 * HH, nullptr, 0, ba, nullptr,
            hs, 2LL * MT * DD, DD);
    }

    // 7. expert down-proj (batched z=8, 2-term): eout_e = hs_e @ w2ts_e^T
    hmma_gemm<TE_STORE><<<dim3(HH / 128, MT / 128, EE), blk, HG_SMEM>>>(
        hs, 2LL * MT * DD, w2ts, 2LL * DD * HH, 2 * DD, eout, (long long)MT * HH, bnone,
        nullptr, nullptr, 0, 0);

    // 8. final reduce: out = x2 + sum_e g_e * (eout_e + b2_e)
    moe_reduce<<<(MT * HH / 4) / 256, blk>>>(x2, eout, g, b2, out);
}

// round 8
// speedup vs baseline: 4.9659x; 1.6135x over previous
#include <cuda_runtime.h>
#include <cuda_bf16.h>
#include <cuda_fp16.h>
#include <cstdint>

// ============================================================================
// TinyTransformerBlock on GB300 (compute_103 PTX -> HMMA fp16 tensor cores).
//  - QKV/O projections: 3-term split  A'=[hi,lo,hi] x B'=[hi,hi,lo], K'=3K
//    (error ~2^-22, negligible) -- keeps attention chain + residual clean.
//  - MoE up/down:       1-term plain fp16 GEMM (error ~2e-4, within budget)
// fp32 accumulation in HMMA. Attention core stays fp32 SGEMM.
// ============================================================================

__device__ __forceinline__ uint32_t smem_to_u32(const void* p) {
    uint32_t a;
    asm("{ .reg .u64 t; cvta.to.shared.u64 t, %1; cvt.u32.u64 %0, t; }" : "=r"(a) : "l"(p));
    return a;
}
__device__ __forceinline__ void cp16(uint32_t saddr, const void* g) {
    asm volatile("cp.async.cg.shared.global [%0], [%1], 16;" :: "r"(saddr), "l"(g));
}
#define CP_COMMIT() asm volatile("cp.async.commit_group;" ::: "memory")
#define CP_WAIT_1() asm volatile("cp.async.wait_group 1;" ::: "memory")

__device__ __forceinline__ void ldm_x4(uint32_t* r, uint32_t addr) {
    asm volatile("ldmatrix.sync.aligned.m8n8.x4.shared.b16 {%0,%1,%2,%3}, [%4];"
        : "=r"(r[0]), "=r"(r[1]), "=r"(r[2]), "=r"(r[3]) : "r"(addr));
}
__device__ __forceinline__ void mma_16816(float* c, const uint32_t* a, uint32_t b0, uint32_t b1) {
    asm volatile("mma.sync.aligned.m16n8k16.row.col.f32.f16.f16.f32 "
        "{%0,%1,%2,%3}, {%4,%5,%6,%7}, {%8,%9}, {%0,%1,%2,%3};"
        : "+f"(c[0]), "+f"(c[1]), "+f"(c[2]), "+f"(c[3])
        : "r"(a[0]), "r"(a[1]), "r"(a[2]), "r"(a[3]), "r"(b0), "r"(b1));
}

// ---------------- problem sizes ----------------
#define MT 4096            // tokens
#define HH 1024            // hidden
#define DD 4096            // expert dim
#define EE 8               // experts
#define SQ 1024            // seq
#define BB 4               // batch

// ---------------- scratch (device globals; allocation-free) ----------------
__device__ __align__(1024) float g_qkv[3ULL * MT * HH];
__device__ __align__(1024) float g_s[(long long)BB * SQ * SQ];
__device__ __align__(1024) float g_a[(long long)MT * HH];
__device__ __align__(1024) float g_x2[(long long)MT * HH];
__device__ __align__(1024) float g_g[(long long)MT * EE];
__device__ __align__(1024) float g_eout[(long long)EE * MT * HH];
__device__ __align__(1024) __half g_xs[(long long)MT * 3 * HH];              // 3-term A
__device__ __align__(1024) __half g_as[(long long)MT * 3 * HH];              // 3-term A
__device__ __align__(1024) __half g_x2s[(long long)MT * HH];                 // 1-term A (fp16)
__device__ __align__(1024) __half g_wts[4ULL * HH * 3 * HH];                 // Wq,Wk,Wv,Wo 3-term B
__device__ __align__(1024) __half g_w1ts[(long long)EE * DD * HH];           // 1-term B
__device__ __align__(1024) __half g_w2ts[(long long)EE * HH * DD];           // 1-term B
__device__ __align__(1024) __half g_hs[(long long)EE * MT * DD];             // 1-term A

struct PtrArr { const float* p[8]; };

// A-side 3-term: [hi, lo, hi]
__device__ __forceinline__ void split3_pairA(float v0, float v1, __half* base,
                                             long long n, long long K) {
    __half h0 = __float2half_rn(v0), h1 = __float2half_rn(v1);
    __half l0 = __float2half_rn(v0 - __half2float(h0));
    __half l1 = __float2half_rn(v1 - __half2float(h1));
    __half2 hh = __halves2half2(h0, h1);
    __half2 ll = __halves2half2(l0, l1);
    *(__half2*)&base[n] = hh;
    *(__half2*)&base[K + n] = ll;
    *(__half2*)&base[2 * K + n] = hh;
}

// ---------------- HMMA GEMM: C[M,N] = A'[M,K'] x B'[N,K']^T ----------------
// CTA 128x128, BK=64, 3-stage cp.async pipe, 8 warps (2M x 4N), warp 64x32.
enum { TE_BIAS = 0, TE_BIAS_RESID_CVT1 = 1, TE_BIAS_RELU_CVT1 = 2, TE_STORE = 3 };

#define HG_STAGE 32768          // A 16KB + B 16KB
#define HG_SMEM (3 * HG_STAGE)

// copy one 128x64 fp16 tile (row0-relative rows) into swizzled smem
__device__ __forceinline__ void load_tile_cp(uint32_t sbase, const __half* g,
                                             long long ld, int row0, int k0, int tid)
{
    const int r = tid >> 1;
    const int c0 = (tid & 1) * 4;
    const __half* gp = g + (long long)(row0 + r) * ld + k0 + c0 * 8;
    const uint32_t srow = sbase + r * 128;
#pragma unroll
    for (int i = 0; i < 4; i++)
        cp16(srow + (((c0 + i) ^ (r & 7)) << 4), gp + i * 8);
}

template <int EPI>
__global__ void __launch_bounds__(256)
hmma_gemm(const __half* __restrict__ A, long long aZ,
          const __half* __restrict__ B, long long bZ,
          int Kp, float* C, long long cZ, PtrArr bias, const float* resid,
          __half* cvt, long long cvtZ, int cvtK)
{
    extern __shared__ __align__(1024) char smem[];
    const uint32_t sb = smem_to_u32(smem);
    const int tid = threadIdx.x;
    const int wid = tid >> 5, lane = tid & 31;
    const int z = blockIdx.z;
    const int m0 = blockIdx.y << 7;
    const int n0 = blockIdx.x << 7;
    const int Nt = gridDim.x << 7;
    const __half* Az = A + (long long)z * aZ;
    const __half* Bz = B + (long long)z * bZ;
    const int nch = Kp >> 6;

    const int wm = (wid >> 2) * 64;     // warp M offset in tile
    const int wn = (wid & 3) * 32;      // warp N offset in tile

    float acc[4][4][4];
#pragma unroll
    for (int i = 0; i < 4; i++)
#pragma unroll
        for (int j = 0; j < 4; j++)
#pragma unroll
            for (int r = 0; r < 4; r++) acc[i][j][r] = 0.0f;

    // prologue: chunks 0,1 -> stages 0,1
    load_tile_cp(sb, Az, Kp, m0, 0, tid);
    load_tile_cp(sb + 16384, Bz, Kp, n0, 0, tid);
    CP_COMMIT();
    load_tile_cp(sb + HG_STAGE, Az, Kp, m0, 64, tid);
    load_tile_cp(sb + HG_STAGE + 16384, Bz, Kp, n0, 64, tid);
    CP_COMMIT();

    // fragment row indices
    const int arow = lane & 15;
    const int ahalf = lane >> 4;
    const int brow = (lane & 7) + ((lane >> 4) & 1) * 8;
    const int bhalf = (lane >> 3) & 1;

    for (int c = 0; c < nch; c++) {
        CP_WAIT_1();
        __syncthreads();
        if (c + 2 < nch) {
            const uint32_t st = sb + ((c + 2) % 3) * HG_STAGE;
            load_tile_cp(st, Az, Kp, m0, (c + 2) * 64, tid);
            load_tile_cp(st + 16384, Bz, Kp, n0, (c + 2) * 64, tid);
        }
        CP_COMMIT();

        const uint32_t sA = sb + (c % 3) * HG_STAGE;
        const uint32_t sB = sA + 16384;
#pragma unroll
        for (int ks = 0; ks < 4; ks++) {
            uint32_t a[4][4];
#pragma unroll
            for (int mi = 0; mi < 4; mi++) {
                const int row = wm + mi * 16 + arow;
                const int ch = ks * 2 + ahalf;
                ldm_x4(a[mi], sA + row * 128 + ((ch ^ (row & 7)) << 4));
            }
            uint32_t b[2][4];
#pragma unroll
            for (int gI = 0; gI < 2; gI++) {
                const int row = wn + gI * 16 + brow;
                const int ch = ks * 2 + bhalf;
                ldm_x4(b[gI], sB + row * 128 + ((ch ^ (row & 7)) << 4));
            }
#pragma unroll
            for (int mi = 0; mi < 4; mi++)
#pragma unroll
                for (int ni = 0; ni < 4; ni++) {
                    const int gI = ni >> 1, off = (ni & 1) * 2;
                    mma_16816(acc[mi][ni], a[mi], b[gI][off], b[gI][off + 1]);
                }
        }
        __syncthreads();
    }

    // ---- epilogue ----
    const int l4 = lane >> 2, l2 = (lane & 3) << 1;
    float* Cz = C + (long long)z * cZ;
    const float* bz = bias.p[z];
    __half* cvz = (EPI == TE_BIAS_RESID_CVT1 || EPI == TE_BIAS_RELU_CVT1)
                      ? cvt + (long long)z * cvtZ : nullptr;

#pragma unroll
    for (int mi = 0; mi < 4; mi++)
#pragma unroll
        for (int h = 0; h < 2; h++) {
            const long long m = (long long)m0 + wm + mi * 16 + l4 + h * 8;
#pragma unroll
            for (int ni = 0; ni < 4; ni++) {
                const long long n = n0 + wn + ni * 8 + l2;
                float v0 = acc[mi][ni][h * 2 + 0];
                float v1 = acc[mi][ni][h * 2 + 1];
                if (EPI != TE_STORE) {
                    v0 += bz[n]; v1 += bz[n + 1];
                }
                if (EPI == TE_BIAS_RELU_CVT1) {
                    v0 = fmaxf(v0, 0.0f); v1 = fmaxf(v1, 0.0f);
                }
                if (EPI == TE_BIAS_RESID_CVT1) {
                    float2 rv = *(const float2*)&resid[m * Nt + n];
                    v0 += rv.x; v1 += rv.y;
                }
                if (EPI == TE_BIAS || EPI == TE_STORE || EPI == TE_BIAS_RESID_CVT1) {
                    float2 o; o.x = v0; o.y = v1;
                    *(float2*)&Cz[m * Nt + n] = o;
                }
                if (EPI == TE_BIAS_RESID_CVT1 || EPI == TE_BIAS_RELU_CVT1) {
                    *(__half2*)&cvz[m * cvtK + n] =
                        __halves2half2(__float2half_rn(v0), __float2half_rn(v1));
                }
            }
        }
}

// ---------------- split helpers ----------------
// A-side 3-term row split: in [M,K] fp32 -> out [M,3K] fp16 [hi, lo, hi]
__global__ void row_split3(const float* __restrict__ in, __half* __restrict__ out, int K)
{
    const long long i = (long long)blockIdx.x * blockDim.x + threadIdx.x;
    const int K4 = K >> 2;
    const long long mrow = i / K4;
    const int k4 = (int)(i % K4) << 2;
    float4 v = *(const float4*)&in[mrow * K + k4];
    __half* o = out + mrow * (3LL * K);
    split3_pairA(v.x, v.y, o, k4, K);
    split3_pairA(v.z, v.w, o, k4 + 2, K);
}

// B-side transpose split: in [K,N] fp32 -> out [N, TERMS*K] fp16
// TERMS==3: [hi, hi, lo]; TERMS==1: [hi]
template <int TERMS>
__global__ void transpose_split(PtrArr in, int K, int N,
                                __half* __restrict__ out, long long outZ)
{
    __shared__ float t[64][65];
    const float* src = in.p[blockIdx.z];
    __half* dst = out + blockIdx.z * outZ;
    const int n0 = blockIdx.x * 64, k0 = blockIdx.y * 64;
    const int tr = threadIdx.x >> 6;      // 0..3
    const int tc = threadIdx.x & 63;      // 0..63
#pragma unroll
    for (int j = 0; j < 16; j++) {
        const int r = tr + j * 4;
        t[r][tc] = src[(long long)(k0 + r) * N + n0 + tc];
    }
    __syncthreads();
#pragma unroll
    for (int j = 0; j < 16; j++) {
        const int rn = tr + j * 4;        // local n
        const float v = t[tc][rn];
        const __half hi = __float2half_rn(v);
        __half* o = dst + (long long)(n0 + rn) * ((long long)TERMS * K) + k0 + tc;
        o[0] = hi;
        if (TERMS == 3) {
            o[K] = hi;
            o[2LL * K] = __float2half_rn(v - __half2float(hi));
        }
    }
}

// ---------------- fp32 attention core ----------------
#define BSM 128
#define BSN 128
#define BSK 8

enum { EPI_NONE = 0, EPI_SCALE = 1 };

template <int EPI, bool TRANSB>
__launch_bounds__(256, 2)
__global__ void sgemm(const float* __restrict__ A, const float* __restrict__ B,
                      float* __restrict__ C, int M, int N, int K,
                      long long sA, long long sB, long long sC, float alpha)
{
    __shared__ float As[BSK][BSM];
    __shared__ float Bs[BSK][BSN];
    const int bz = blockIdx.z;
    A += (long long)bz * sA; B += (long long)bz * sB; C += (long long)bz * sC;
    const int row0 = blockIdx.y * BSM, col0 = blockIdx.x * BSN;
    const int tid = threadIdx.x;
    const int tx = tid & 15, ty = tid >> 4;
    const int arow = tid >> 1, acol = (tid & 1) * 4;
    const float* Aptr = A + (long long)(row0 + arow) * K + acol;
    const int bnrow = tid >> 5, bncol = (tid & 31) * 4;
    const int btn = tid >> 1, btk = (tid & 1) * 4;
    const float* Bptr = TRANSB ? B + (long long)(col0 + btn) * K + btk
                               : B + (long long)bnrow * N + col0 + bncol;
    float acc[8][8];
#pragma unroll
    for (int i = 0; i < 8; i++)
#pragma unroll
        for (int j = 0; j < 8; j++) acc[i][j] = 0.0f;

    for (int k0 = 0; k0 < K; k0 += BSK) {
        float4 av = *(const float4*)Aptr;
        As[acol + 0][arow] = av.x; As[acol + 1][arow] = av.y;
        As[acol + 2][arow] = av.z; As[acol + 3][arow] = av.w;
        float4 bv = *(const float4*)Bptr;
        if (TRANSB) {
            Bs[btk + 0][btn] = bv.x; Bs[btk + 1][btn] = bv.y;
            Bs[btk + 2][btn] = bv.z; Bs[btk + 3][btn] = bv.w;
        } else {
            *(float4*)&Bs[bnrow][bncol] = bv;
        }
        __syncthreads();
#pragma unroll
        for (int kk = 0; kk < BSK; kk++) {
            float a[8], b[8];
            *(float4*)&a[0] = *(const float4*)&As[kk][ty * 8];
            *(float4*)&a[4] = *(const float4*)&As[kk][ty * 8 + 4];
            *(float4*)&b[0] = *(const float4*)&Bs[kk][tx * 8];
            *(float4*)&b[4] = *(const float4*)&Bs[kk][tx * 8 + 4];
#pragma unroll
            for (int i = 0; i < 8; i++)
#pragma unroll
                for (int j = 0; j < 8; j++) acc[i][j] = fmaf(a[i], b[j], acc[i][j]);
        }
        __syncthreads();
        Aptr += BSK;
        if (TRANSB) Bptr += BSK; else Bptr += (long long)BSK * N;
    }
#pragma unroll
    for (int i = 0; i < 8; i++) {
        const int m = row0 + ty * 8 + i;
#pragma unroll
        for (int j = 0; j < 8; j += 4) {
            const int n = col0 + tx * 8 + j;
            float r0 = acc[i][j], r1 = acc[i][j + 1], r2 = acc[i][j + 2], r3 = acc[i][j + 3];
            if (EPI == EPI_SCALE) { r0 *= alpha; r1 *= alpha; r2 *= alpha; r3 *= alpha; }
            *(float4*)&C[(long long)m * N + n] = make_float4(r0, r1, r2, r3);
        }
    }
}

__global__ void softmax_rows(float* __restrict__ S, int ncols)
{
    const int row = blockIdx.x;
    float* p = S + (long long)row * ncols;
    const int tid = threadIdx.x;
    __shared__ float red[256];
    float m = -1e30f;
    for (int c = tid; c < ncols; c += 256) m = fmaxf(m, p[c]);
    red[tid] = m; __syncthreads();
    for (int s = 128; s > 0; s >>= 1) { if (tid < s) red[tid] = fmaxf(red[tid], red[tid + s]); __syncthreads(); }
    m = red[0]; __syncthreads();
    float sum = 0.0f;
    for (int c = tid; c < ncols; c += 256) { float e = __expf(p[c] - m); p[c] = e; sum += e; }
    red[tid] = sum; __syncthreads();
    for (int s = 128; s > 0; s >>= 1) { if (tid < s) red[tid] += red[tid + s]; __syncthreads(); }
    const float inv = 1.0f / red[0];
    for (int c = tid; c < ncols; c += 256) p[c] *= inv;
}

__global__ void gates_kernel(const float* __restrict__ x2, const float* __restrict__ Wg,
                             const float* __restrict__ bg, float* __restrict__ G)
{
    const int row = blockIdx.x;
    const int tid = threadIdx.x;
    const float* xp = x2 + (long long)row * HH;
    float part[8];
#pragma unroll
    for (int e = 0; e < 8; e++) part[e] = 0.0f;
    for (int h = tid; h < HH; h += 256) {
        float xv = xp[h];
#pragma unroll
        for (int e = 0; e < 8; e++) part[e] = fmaf(xv, Wg[h * 8 + e], part[e]);
    }
    __shared__ float red[256];
    __shared__ float logits[8];
#pragma unroll
    for (int e = 0; e < 8; e++) {
        red[tid] = part[e]; __syncthreads();
        for (int s = 128; s > 0; s >>= 1) { if (tid < s) red[tid] += red[tid + s]; __syncthreads(); }
        if (tid == 0) logits[e] = red[0] + bg[e];
        __syncthreads();
    }
    if (tid == 0) {
        float m = -1e30f;
#pragma unroll
        for (int e = 0; e < 8; e++) m = fmaxf(m, logits[e]);
        float ex[8], s = 0.0f;
#pragma unroll
        for (int e = 0; e < 8; e++) { ex[e] = __expf(logits[e] - m); s += ex[e]; }
        const float inv = 1.0f / s;
#pragma unroll
        for (int e = 0; e < 8; e++) G[row * 8 + e] = ex[e] * inv;
    }
}

// out[m,n] = x2[m,n] + sum_e g[m,e] * (eout[e][m,n] + b2[e][n])
__global__ void moe_reduce(const float* __restrict__ x2, const float* __restrict__ eout,
                           const float* __restrict__ g, const float* __restrict__ b2,
                           float* __restrict__ out)
{
    const long long i = (long long)blockIdx.x * blockDim.x + threadIdx.x;
    const long long m = i / (HH / 4);
    const int n4 = (int)(i % (HH / 4)) << 2;
    float4 acc = *(const float4*)&x2[m * HH + n4];
#pragma unroll
    for (int e = 0; e < 8; e++) {
        const float ge = g[m * 8 + e];
        float4 eo = *(const float4*)&eout[((long long)e * MT + m) * HH + n4];
        float4 b = *(const float4*)&b2[e * HH + n4];
        acc.x += ge * (eo.x + b.x); acc.y += ge * (eo.y + b.y);
        acc.z += ge * (eo.z + b.z); acc.w += ge * (eo.w + b.w);
    }
    *(float4*)&out[m * HH + n4] = acc;
}

// ---------------- host side ----------------
extern "C" void kernel_launch(void* const* d_in, const int* in_sizes, int n_in,
                              void* d_out, int out_size)
{
    const float* x  = (const float*)d_in[0];
    const float* Wq = (const float*)d_in[1];
    const float* bq = (const float*)d_in[2];
    const float* Wk = (const float*)d_in[3];
    const float* bk = (const float*)d_in[4];
    const float* Wv = (const float*)d_in[5];
    const float* bv = (const float*)d_in[6];
    const float* Wo = (const float*)d_in[7];
    const float* bo = (const float*)d_in[8];
    const float* Wg = (const float*)d_in[9];
    const float* bg = (const float*)d_in[10];
    const float* W1 = (const float*)d_in[11];
    const float* b1 = (const float*)d_in[12];
    const float* W2 = (const float*)d_in[13];
    const float* b2 = (const float*)d_in[14];
    float* out = (float*)d_out;

    float *qkv, *s, *a, *x2, *g, *eout;
    __half *xs, *as, *x2s, *wts, *w1ts, *w2ts, *hs;
    cudaGetSymbolAddress((void**)&qkv, g_qkv);
    cudaGetSymbolAddress((void**)&s, g_s);
    cudaGetSymbolAddress((void**)&a, g_a);
    cudaGetSymbolAddress((void**)&x2, g_x2);
    cudaGetSymbolAddress((void**)&g, g_g);
    cudaGetSymbolAddress((void**)&eout, g_eout);
    cudaGetSymbolAddress((void**)&xs, g_xs);
    cudaGetSymbolAddress((void**)&as, g_as);
    cudaGetSymbolAddress((void**)&x2s, g_x2s);
    cudaGetSymbolAddress((void**)&wts, g_wts);
    cudaGetSymbolAddress((void**)&w1ts, g_w1ts);
    cudaGetSymbolAddress((void**)&w2ts, g_w2ts);
    cudaGetSymbolAddress((void**)&hs, g_hs);

    cudaFuncSetAttribute(hmma_gemm<TE_BIAS>, cudaFuncAttributeMaxDynamicSharedMemorySize, HG_SMEM);
    cudaFuncSetAttribute(hmma_gemm<TE_BIAS_RESID_CVT1>, cudaFuncAttributeMaxDynamicSharedMemorySize, HG_SMEM);
    cudaFuncSetAttribute(hmma_gemm<TE_BIAS_RELU_CVT1>, cudaFuncAttributeMaxDynamicSharedMemorySize, HG_SMEM);
    cudaFuncSetAttribute(hmma_gemm<TE_STORE>, cudaFuncAttributeMaxDynamicSharedMemorySize, HG_SMEM);

    PtrArr bnone = {};
    dim3 blk(256);

    // 1. splits of inputs / weights
    row_split3<<<(MT * HH / 4) / 256, blk>>>(x, xs, HH);
    {
        PtrArr wi; wi.p[0] = Wq; wi.p[1] = Wk; wi.p[2] = Wv; wi.p[3] = Wo;
        transpose_split<3><<<dim3(HH / 64, HH / 64, 4), blk>>>(wi, HH, HH, wts, 3LL * HH * HH);
    }
    {
        PtrArr wi;
        for (int e = 0; e < 8; e++) wi.p[e] = W1 + (long long)e * HH * DD;
        transpose_split<1><<<dim3(DD / 64, HH / 64, EE), blk>>>(wi, HH, DD, w1ts, (long long)HH * DD);
    }
    {
        PtrArr wi;
        for (int e = 0; e < 8; e++) wi.p[e] = W2 + (long long)e * DD * HH;
        transpose_split<1><<<dim3(HH / 64, DD / 64, EE), blk>>>(wi, DD, HH, w2ts, (long long)DD * HH);
    }

    // 2. QKV projections (batched z=3, 3-term): qkv_z = xs @ wts_z^T + b_z
    {
        PtrArr ba; ba.p[0] = bq; ba.p[1] = bk; ba.p[2] = bv;
        hmma_gemm<TE_BIAS><<<dim3(HH / 128, MT / 128, 3), blk, HG_SMEM>>>(
            xs, 0, wts, 3LL * HH * HH, 3 * HH, qkv, (long long)MT * HH, ba,
            nullptr, nullptr, 0, 0);
    }
    const float* q = qkv;
    const float* kk2 = qkv + (long long)MT * HH;
    const float* v = qkv + 2LL * MT * HH;

    // 3. attention core (fp32)
    sgemm<EPI_SCALE, true><<<dim3(SQ / BSN, SQ / BSM, BB), blk>>>(
        q, kk2, s, SQ, SQ, HH, (long long)SQ * HH, (long long)SQ * HH, (long long)SQ * SQ, 0.03125f);
    softmax_rows<<<BB * SQ, 256>>>(s, SQ);
    sgemm<EPI_NONE, false><<<dim3(HH / BSN, SQ / BSM, BB), blk>>>(
        s, v, a, SQ, HH, SQ, (long long)SQ * SQ, (long long)SQ * HH, (long long)SQ * HH, 1.0f);

    // 4. O projection + residual -> x2 (fp32) and x2s (fp16 cvt)
    row_split3<<<(MT * HH / 4) / 256, blk>>>(a, as, HH);
    {
        PtrArr ba; ba.p[0] = bo;
        hmma_gemm<TE_BIAS_RESID_CVT1><<<dim3(HH / 128, MT / 128, 1), blk, HG_SMEM>>>(
            as, 0, wts + 3ULL * HH * HH * 3, 0, 3 * HH, x2, 0, ba, x, x2s, 0, HH);
    }

    // 5. gates
    gates_kernel<<<MT, 256>>>(x2, Wg, bg, g);

    // 6. expert up-proj (batched z=8, fp16): hs_e = fp16(relu(x2s @ w1ts_e^T + b1_e))
    {
        PtrArr ba;
        for (int e = 0; e < 8; e++) ba.p[e] = b1 + (long long)e * DD;
        hmma_gemm<TE_BIAS_RELU_CVT1><<<dim3(DD / 128, MT / 128, EE), blk, HG_SMEM>>>(
            x2s, 0, w1ts, (long long)HH * DD, HH, nullptr, 0, ba, nullptr,
            hs, (long long)MT * DD, DD);
    }

    // 7. expert down-proj (batched z=8, fp16): eout_e = hs_e @ w2ts_e^T
    hmma_gemm<TE_STORE><<<dim3(HH / 128, MT / 128, EE), blk, HG_SMEM>>>(
        hs, (long long)MT * DD, w2ts, (long long)DD * HH, DD, eout, (long long)MT * HH, bnone,
        nullptr, nullptr, 0, 0);

    // 8. final reduce: out = x2 + sum_e g_e * (eout_e + b2_e)
    moe_reduce<<<(MT * HH / 4) / 256, blk>>>(x2, eout, g, b2, out);
}

// round 11
// speedup vs baseline: 5.3559x; 1.0785x over previous
#include <cuda_runtime.h>
#include <cuda_bf16.h>
#include <cuda_fp16.h>
#include <cstdint>

// ============================================================================
// TinyTransformerBlock on GB300 (compute_103 PTX -> HMMA fp16 tensor cores).
//  - QKV/O projections:  3-term split A'=[hi,lo,hi] x B'=[hi,hi,lo], K'=3K
//  - Attention QK^T, PV: 3-term split fp16 HMMA (error ~2^-22)
//  - MoE up/down:        1-term plain fp16 GEMM (error ~2e-4, within budget)
//  - MoE gating fused into down-proj epilogue via atomic RED.ADD
// fp32 accumulation in all HMMA. Softmax/gates fp32.
// ============================================================================

__device__ __forceinline__ uint32_t smem_to_u32(const void* p) {
    uint32_t a;
    asm("{ .reg .u64 t; cvta.to.shared.u64 t, %1; cvt.u32.u64 %0, t; }" : "=r"(a) : "l"(p));
    return a;
}
__device__ __forceinline__ void cp16(uint32_t saddr, const void* g) {
    asm volatile("cp.async.cg.shared.global [%0], [%1], 16;" :: "r"(saddr), "l"(g));
}
#define CP_COMMIT() asm volatile("cp.async.commit_group;" ::: "memory")
#define CP_WAIT_1() asm volatile("cp.async.wait_group 1;" ::: "memory")

__device__ __forceinline__ void ldm_x4(uint32_t* r, uint32_t addr) {
    asm volatile("ldmatrix.sync.aligned.m8n8.x4.shared.b16 {%0,%1,%2,%3}, [%4];"
        : "=r"(r[0]), "=r"(r[1]), "=r"(r[2]), "=r"(r[3]) : "r"(addr));
}
__device__ __forceinline__ void mma_16816(float* c, const uint32_t* a, uint32_t b0, uint32_t b1) {
    asm volatile("mma.sync.aligned.m16n8k16.row.col.f32.f16.f16.f32 "
        "{%0,%1,%2,%3}, {%4,%5,%6,%7}, {%8,%9}, {%0,%1,%2,%3};"
        : "+f"(c[0]), "+f"(c[1]), "+f"(c[2]), "+f"(c[3])
        : "r"(a[0]), "r"(a[1]), "r"(a[2]), "r"(a[3]), "r"(b0), "r"(b1));
}

// ---------------- problem sizes ----------------
#define MT 4096            // tokens
#define HH 1024            // hidden
#define DD 4096            // expert dim
#define EE 8               // experts
#define SQ 1024            // seq
#define BB 4               // batch

// ---------------- scratch (device globals; allocation-free) ----------------
__device__ __align__(1024) float g_qkv[3ULL * MT * HH];
__device__ __align__(1024) float g_s[(long long)BB * SQ * SQ];
__device__ __align__(1024) float g_a[(long long)MT * HH];
__device__ __align__(1024) float g_x2[(long long)MT * HH];
__device__ __align__(1024) float g_g[(long long)MT * EE];
__device__ __align__(1024) __half g_xs[(long long)MT * 3 * HH];       // QKV A-split; later q A-split
__device__ __align__(1024) __half g_as[(long long)MT * 3 * HH];       // k B-split; later a A-split
__device__ __align__(1024) __half g_ps[(long long)MT * 3 * SQ];       // probs A-split
__device__ __align__(1024) __half g_vts[(long long)BB * HH * 3 * SQ]; // V^T B-split
__device__ __align__(1024) __half g_x2s[(long long)MT * HH];          // 1-term A
__device__ __align__(1024) __half g_wts[4ULL * HH * 3 * HH];          // Wq,Wk,Wv,Wo 3-term B
__device__ __align__(1024) __half g_w1ts[(long long)EE * DD * HH];    // 1-term B
__device__ __align__(1024) __half g_w2ts[(long long)EE * HH * DD];    // 1-term B
__device__ __align__(1024) __half g_hs[(long long)EE * MT * DD];      // 1-term A

struct PtrArr { const float* p[8]; };

// A-side 3-term: [hi, lo, hi]
__device__ __forceinline__ void split3_pairA(float v0, float v1, __half* base,
                                             long long n, long long K) {
    __half h0 = __float2half_rn(v0), h1 = __float2half_rn(v1);
    __half l0 = __float2half_rn(v0 - __half2float(h0));
    __half l1 = __float2half_rn(v1 - __half2float(h1));
    __half2 hh = __halves2half2(h0, h1);
    __half2 ll = __halves2half2(l0, l1);
    *(__half2*)&base[n] = hh;
    *(__half2*)&base[K + n] = ll;
    *(__half2*)&base[2 * K + n] = hh;
}
// B-side 3-term: [hi, hi, lo]
__device__ __forceinline__ void split3_pairB(float v0, float v1, __half* base,
                                             long long n, long long K) {
    __half h0 = __float2half_rn(v0), h1 = __float2half_rn(v1);
    __half l0 = __float2half_rn(v0 - __half2float(h0));
    __half l1 = __float2half_rn(v1 - __half2float(h1));
    __half2 hh = __halves2half2(h0, h1);
    __half2 ll = __halves2half2(l0, l1);
    *(__half2*)&base[n] = hh;
    *(__half2*)&base[K + n] = hh;
    *(__half2*)&base[2 * K + n] = ll;
}

// ---------------- HMMA GEMM: C[M,N] = A'[M,K'] x B'[N,K']^T ----------------
// CTA 128x128, BK=64, 3-stage cp.async pipe, 8 warps (2M x 4N), warp 64x32.
enum { TE_BIAS = 0, TE_BIAS_RESID_CVT1 = 1, TE_BIAS_RELU_CVT1 = 2,
       TE_STORE = 3, TE_SCALE = 4, TE_GATED_RED = 5 };

#define HG_STAGE 32768          // A 16KB + B 16KB
#define HG_SMEM (3 * HG_STAGE)

__device__ __forceinline__ void load_tile_cp(uint32_t sbase, const __half* g,
                                             long long ld, int row0, int k0, int tid)
{
    const int r = tid >> 1;
    const int c0 = (tid & 1) * 4;
    const __half* gp = g + (long long)(row0 + r) * ld + k0 + c0 * 8;
    const uint32_t srow = sbase + r * 128;
#pragma unroll
    for (int i = 0; i < 4; i++)
        cp16(srow + (((c0 + i) ^ (r & 7)) << 4), gp + i * 8);
}

template <int EPI>
__global__ void __launch_bounds__(256)
hmma_gemm(const __half* __restrict__ A, long long aZ,
          const __half* __restrict__ B, long long bZ,
          int Kp, float* C, long long cZ, PtrArr bias, const float* resid,
          __half* cvt, long long cvtZ, int cvtK,
          const float* __restrict__ gate, float alpha)
{
    extern __shared__ __align__(1024) char smem[];
    const uint32_t sb = smem_to_u32(smem);
    const int tid = threadIdx.x;
    const int wid = tid >> 5, lane = tid & 31;
    const int z = blockIdx.z;
    const int m0 = blockIdx.y << 7;
    const int n0 = blockIdx.x << 7;
    const int Nt = gridDim.x << 7;
    const __half* Az = A + (long long)z * aZ;
    const __half* Bz = B + (long long)z * bZ;
    const int nch = Kp >> 6;

    const int wm = (wid >> 2) * 64;
    const int wn = (wid & 3) * 32;

    float acc[4][4][4];
#pragma unroll
    for (int i = 0; i < 4; i++)
#pragma unroll
        for (int j = 0; j < 4; j++)
#pragma unroll
            for (int r = 0; r < 4; r++) acc[i][j][r] = 0.0f;

    load_tile_cp(sb, Az, Kp, m0, 0, tid);
    load_tile_cp(sb + 16384, Bz, Kp, n0, 0, tid);
    CP_COMMIT();
    load_tile_cp(sb + HG_STAGE, Az, Kp, m0, 64, tid);
    load_tile_cp(sb + HG_STAGE + 16384, Bz, Kp, n0, 64, tid);
    CP_COMMIT();

    const int arow = lane & 15;
    const int ahalf = lane >> 4;
    const int brow = (lane & 7) + ((lane >> 4) & 1) * 8;
    const int bhalf = (lane >> 3) & 1;

    for (int c = 0; c < nch; c++) {
        CP_WAIT_1();
        __syncthreads();
        if (c + 2 < nch) {
            const uint32_t st = sb + ((c + 2) % 3) * HG_STAGE;
            load_tile_cp(st, Az, Kp, m0, (c + 2) * 64, tid);
            load_tile_cp(st + 16384, Bz, Kp, n0, (c + 2) * 64, tid);
        }
        CP_COMMIT();

        const uint32_t sA = sb + (c % 3) * HG_STAGE;
        const uint32_t sB = sA + 16384;
#pragma unroll
        for (int ks = 0; ks < 4; ks++) {
            uint32_t a[4][4];
#pragma unroll
            for (int mi = 0; mi < 4; mi++) {
                const int row = wm + mi * 16 + arow;
                const int ch = ks * 2 + ahalf;
                ldm_x4(a[mi], sA + row * 128 + ((ch ^ (row & 7)) << 4));
            }
            uint32_t b[2][4];
#pragma unroll
            for (int gI = 0; gI < 2; gI++) {
                const int row = wn + gI * 16 + brow;
                const int ch = ks * 2 + bhalf;
                ldm_x4(b[gI], sB + row * 128 + ((ch ^ (row & 7)) << 4));
            }
#pragma unroll
            for (int mi = 0; mi < 4; mi++)
#pragma unroll
                for (int ni = 0; ni < 4; ni++) {
                    const int gI = ni >> 1, off = (ni & 1) * 2;
                    mma_16816(acc[mi][ni], a[mi], b[gI][off], b[gI][off + 1]);
                }
        }
        __syncthreads();
    }

    // ---- epilogue ----
    const int l4 = lane >> 2, l2 = (lane & 3) << 1;
    float* Cz = C + (long long)z * cZ;
    const float* bz = bias.p[z];
    __half* cvz = (EPI == TE_BIAS_RESID_CVT1 || EPI == TE_BIAS_RELU_CVT1)
                      ? cvt + (long long)z * cvtZ : nullptr;

#pragma unroll
    for (int mi = 0; mi < 4; mi++)
#pragma unroll
        for (int h = 0; h < 2; h++) {
            const long long m = (long long)m0 + wm + mi * 16 + l4 + h * 8;
            float ge = 0.0f;
            if (EPI == TE_GATED_RED) ge = gate[m * EE + z];
#pragma unroll
            for (int ni = 0; ni < 4; ni++) {
                const long long n = n0 + wn + ni * 8 + l2;
                float v0 = acc[mi][ni][h * 2 + 0];
                float v1 = acc[mi][ni][h * 2 + 1];
                if (EPI == TE_BIAS || EPI == TE_BIAS_RESID_CVT1 || EPI == TE_BIAS_RELU_CVT1) {
                    v0 += bz[n]; v1 += bz[n + 1];
                }
                if (EPI == TE_SCALE) { v0 *= alpha; v1 *= alpha; }
                if (EPI == TE_BIAS_RELU_CVT1) {
                    v0 = fmaxf(v0, 0.0f); v1 = fmaxf(v1, 0.0f);
                }
                if (EPI == TE_BIAS_RESID_CVT1) {
                    float2 rv = *(const float2*)&resid[m * Nt + n];
                    v0 += rv.x; v1 += rv.y;
                }
                if (EPI == TE_BIAS || EPI == TE_STORE || EPI == TE_SCALE ||
                    EPI == TE_BIAS_RESID_CVT1) {
                    float2 o; o.x = v0; o.y = v1;
                    *(float2*)&Cz[m * Nt + n] = o;
                }
                if (EPI == TE_GATED_RED) {
                    atomicAdd(&Cz[m * Nt + n], ge * v0);
                    atomicAdd(&Cz[m * Nt + n + 1], ge * v1);
                }
                if (EPI == TE_BIAS_RESID_CVT1 || EPI == TE_BIAS_RELU_CVT1) {
                    *(__half2*)&cvz[m * cvtK + n] =
                        __halves2half2(__float2half_rn(v0), __float2half_rn(v1));
                }
            }
        }
}

// ---------------- split helpers ----------------
// A-side 3-term row split: in [M,K] fp32 -> out [M,3K] fp16 [hi, lo, hi]
__global__ void row_split3(const float* __restrict__ in, __half* __restrict__ out, int K)
{
    const long long i = (long long)blockIdx.x * blockDim.x + threadIdx.x;
    const int K4 = K >> 2;
    const long long mrow = i / K4;
    const int k4 = (int)(i % K4) << 2;
    float4 v = *(const float4*)&in[mrow * K + k4];
    __half* o = out + mrow * (3LL * K);
    split3_pairA(v.x, v.y, o, k4, K);
    split3_pairA(v.z, v.w, o, k4 + 2, K);
}
// B-side 3-term row split: in [M,K] fp32 -> out [M,3K] fp16 [hi, hi, lo]
__global__ void row_split3B(const float* __restrict__ in, __half* __restrict__ out, int K)
{
    const long long i = (long long)blockIdx.x * blockDim.x + threadIdx.x;
    const int K4 = K >> 2;
    const long long mrow = i / K4;
    const int k4 = (int)(i % K4) << 2;
    float4 v = *(const float4*)&in[mrow * K + k4];
    __half* o = out + mrow * (3LL * K);
    split3_pairB(v.x, v.y, o, k4, K);
    split3_pairB(v.z, v.w, o, k4 + 2, K);
}

// B-side transpose split: in [K,N] fp32 -> out [N, TERMS*K] fp16
// TERMS==3: [hi, hi, lo]; TERMS==1: [hi]
template <int TERMS>
__global__ void transpose_split(PtrArr in, int K, int N,
                                __half* __restrict__ out, long long outZ)
{
    __shared__ float t[64][65];
    const float* src = in.p[blockIdx.z];
    __half* dst = out + blockIdx.z * outZ;
    const int n0 = blockIdx.x * 64, k0 = blockIdx.y * 64;
    const int tr = threadIdx.x >> 6;
    const int tc = threadIdx.x & 63;
#pragma unroll
    for (int j = 0; j < 16; j++) {
        const int r = tr + j * 4;
        t[r][tc] = src[(long long)(k0 + r) * N + n0 + tc];
    }
    __syncthreads();
#pragma unroll
    for (int j = 0; j < 16; j++) {
        const int rn = tr + j * 4;
        const float v = t[tc][rn];
        const __half hi = __float2half_rn(v);
        __half* o = dst + (long long)(n0 + rn) * ((long long)TERMS * K) + k0 + tc;
        o[0] = hi;
        if (TERMS == 3) {
            o[K] = hi;
            o[2LL * K] = __float2half_rn(v - __half2float(hi));
        }
    }
}

__global__ void softmax_rows(float* __restrict__ S, int ncols)
{
    const int row = blockIdx.x;
    float* p = S + (long long)row * ncols;
    const int tid = threadIdx.x;
    __shared__ float red[256];
    float m = -1e30f;
    for (int c = tid; c < ncols; c += 256) m = fmaxf(m, p[c]);
    red[tid] = m; __syncthreads();
    for (int s = 128; s > 0; s >>= 1) { if (tid < s) red[tid] = fmaxf(red[tid], red[tid + s]); __syncthreads(); }
    m = red[0]; __syncthreads();
    float sum = 0.0f;
    for (int c = tid; c < ncols; c += 256) { float e = __expf(p[c] - m); p[c] = e; sum += e; }
    red[tid] = sum; __syncthreads();
    for (int s = 128; s > 0; s >>= 1) { if (tid < s) red[tid] += red[tid + s]; __syncthreads(); }
    const float inv = 1.0f / red[0];
    for (int c = tid; c < ncols; c += 256) p[c] *= inv;
}

__global__ void gates_kernel(const float* __restrict__ x2, const float* __restrict__ Wg,
                             const float* __restrict__ bg, float* __restrict__ G)
{
    const int row = blockIdx.x;
    const int tid = threadIdx.x;
    const float* xp = x2 + (long long)row * HH;
    float part[8];
#pragma unroll
    for (int e = 0; e < 8; e++) part[e] = 0.0f;
    for (int h = tid; h < HH; h += 256) {
        float xv = xp[h];
#pragma unroll
        for (int e = 0; e < 8; e++) part[e] = fmaf(xv, Wg[h * 8 + e], part[e]);
    }
    __shared__ float red[256];
    __shared__ float logits[8];
#pragma unroll
    for (int e = 0; e < 8; e++) {
        red[tid] = part[e]; __syncthreads();
        for (int s = 128; s > 0; s >>= 1) { if (tid < s) red[tid] += red[tid + s]; __syncthreads(); }
        if (tid == 0) logits[e] = red[0] + bg[e];
        __syncthreads();
    }
    if (tid == 0) {
        float m = -1e30f;
#pragma unroll
        for (int e = 0; e < 8; e++) m = fmaxf(m, logits[e]);
        float ex[8], s = 0.0f;
#pragma unroll
        for (int e = 0; e < 8; e++) { ex[e] = __expf(logits[e] - m); s += ex[e]; }
        const float inv = 1.0f / s;
#pragma unroll
        for (int e = 0; e < 8; e++) G[row * 8 + e] = ex[e] * inv;
    }
}

// out[m,n] = x2[m,n] + sum_e g[m,e] * b2[e][n]   (base for gated RED accumulation)
__global__ void out_init(const float* __restrict__ x2, const float* __restrict__ g,
                         const float* __restrict__ b2, float* __restrict__ out)
{
    const long long i = (long long)blockIdx.x * blockDim.x + threadIdx.x;
    const long long m = i / (HH / 4);
    const int n4 = (int)(i % (HH / 4)) << 2;
    float4 acc = *(const float4*)&x2[m * HH + n4];
#pragma unroll
    for (int e = 0; e < 8; e++) {
        const float ge = g[m * 8 + e];
        float4 b = *(const float4*)&b2[e * HH + n4];
        acc.x += ge * b.x; acc.y += ge * b.y;
        acc.z += ge * b.z; acc.w += ge * b.w;
    }
    *(float4*)&out[m * HH + n4] = acc;
}

// ---------------- host side ----------------
extern "C" void kernel_launch(void* const* d_in, const int* in_sizes, int n_in,
                              void* d_out, int out_size)
{
    const float* x  = (const float*)d_in[0];
    const float* Wq = (const float*)d_in[1];
    const float* bq = (const float*)d_in[2];
    const float* Wk = (const float*)d_in[3];
    const float* bk = (const float*)d_in[4];
    const float* Wv = (const float*)d_in[5];
    const float* bv = (const float*)d_in[6];
    const float* Wo = (const float*)d_in[7];
    const float* bo = (const float*)d_in[8];
    const float* Wg = (const float*)d_in[9];
    const float* bg = (const float*)d_in[10];
    const float* W1 = (const float*)d_in[11];
    const float* b1 = (const float*)d_in[12];
    const float* W2 = (const float*)d_in[13];
    const float* b2 = (const float*)d_in[14];
    float* out = (float*)d_out;

    float *qkv, *s, *a, *x2, *g;
    __half *xs, *as, *ps, *vts, *x2s, *wts, *w1ts, *w2ts, *hs;
    cudaGetSymbolAddress((void**)&qkv, g_qkv);
    cudaGetSymbolAddress((void**)&s, g_s);
    cudaGetSymbolAddress((void**)&a, g_a);
    cudaGetSymbolAddress((void**)&x2, g_x2);
    cudaGetSymbolAddress((void**)&g, g_g);
    cudaGetSymbolAddress((void**)&xs, g_xs);
    cudaGetSymbolAddress((void**)&as, g_as);
    cudaGetSymbolAddress((void**)&ps, g_ps);
    cudaGetSymbolAddress((void**)&vts, g_vts);
    cudaGetSymbolAddress((void**)&x2s, g_x2s);
    cudaGetSymbolAddress((void**)&wts, g_wts);
    cudaGetSymbolAddress((void**)&w1ts, g_w1ts);
    cudaGetSymbolAddress((void**)&w2ts, g_w2ts);
    cudaGetSymbolAddress((void**)&hs, g_hs);

    cudaFuncSetAttribute(hmma_gemm<TE_BIAS>, cudaFuncAttributeMaxDynamicSharedMemorySize, HG_SMEM);
    cudaFuncSetAttribute(hmma_gemm<TE_BIAS_RESID_CVT1>, cudaFuncAttributeMaxDynamicSharedMemorySize, HG_SMEM);
    cudaFuncSetAttribute(hmma_gemm<TE_BIAS_RELU_CVT1>, cudaFuncAttributeMaxDynamicSharedMemorySize, HG_SMEM);
    cudaFuncSetAttribute(hmma_gemm<TE_STORE>, cudaFuncAttributeMaxDynamicSharedMemorySize, HG_SMEM);
    cudaFuncSetAttribute(hmma_gemm<TE_SCALE>, cudaFuncAttributeMaxDynamicSharedMemorySize, HG_SMEM);
    cudaFuncSetAttribute(hmma_gemm<TE_GATED_RED>, cudaFuncAttributeMaxDynamicSharedMemorySize, HG_SMEM);

    PtrArr bnone = {};
    dim3 blk(256);

    // 1. splits of inputs / weights
    row_split3<<<(MT * HH / 4) / 256, blk>>>(x, xs, HH);
    {
        PtrArr wi; wi.p[0] = Wq; wi.p[1] = Wk; wi.p[2] = Wv; wi.p[3] = Wo;
        transpose_split<3><<<dim3(HH / 64, HH / 64, 4), blk>>>(wi, HH, HH, wts, 3LL * HH * HH);
    }
    {
        PtrArr wi;
        for (int e = 0; e < 8; e++) wi.p[e] = W1 + (long long)e * HH * DD;
        transpose_split<1><<<dim3(DD / 64, HH / 64, EE), blk>>>(wi, HH, DD, w1ts, (long long)HH * DD);
    }
    {
        PtrArr wi;
        for (int e = 0; e < 8; e++) wi.p[e] = W2 + (long long)e * DD * HH;
        transpose_split<1><<<dim3(HH / 64, DD / 64, EE), blk>>>(wi, DD, HH, w2ts, (long long)DD * HH);
    }

    // 2. QKV projections (batched z=3, 3-term)
    {
        PtrArr ba; ba.p[0] = bq; ba.p[1] = bk; ba.p[2] = bv;
        hmma_gemm<TE_BIAS><<<dim3(HH / 128, MT / 128, 3), blk, HG_SMEM>>>(
            xs, 0, wts, 3LL * HH * HH, 3 * HH, qkv, (long long)MT * HH, ba,
            nullptr, nullptr, 0, 0, nullptr, 0.0f);
    }
    const float* q = qkv;
    const float* kk2 = qkv + (long long)MT * HH;
    const float* v = qkv + 2LL * MT * HH;

    // 3. attention core (fp16 HMMA, 3-term)
    // q A-split into xs (dead after QKV), k B-split into as (dead until step 4)
    row_split3<<<(MT * HH / 4) / 256, blk>>>(q, xs, HH);
    row_split3B<<<(MT * HH / 4) / 256, blk>>>(kk2, as, HH);
    hmma_gemm<TE_SCALE><<<dim3(SQ / 128, SQ / 128, BB), blk, HG_SMEM>>>(
        xs, (long long)SQ * 3 * HH, as, (long long)SQ * 3 * HH, 3 * HH,
        s, (long long)SQ * SQ, bnone, nullptr, nullptr, 0, 0, nullptr, 0.03125f);
    softmax_rows<<<BB * SQ, 256>>>(s, SQ);
    // probs A-split, V^T B-split
    row_split3<<<((long long)MT * SQ / 4) / 256, blk>>>(s, ps, SQ);
    {
        PtrArr vi;
        for (int b = 0; b < BB; b++) vi.p[b] = v + (long long)b * SQ * HH;
        transpose_split<3><<<dim3(HH / 64, SQ / 64, BB), blk>>>(vi, SQ, HH, vts, (long long)HH * 3 * SQ);
    }
    hmma_gemm<TE_STORE><<<dim3(HH / 128, SQ / 128, BB), blk, HG_SMEM>>>(
        ps, (long long)SQ * 3 * SQ, vts, (long long)HH * 3 * SQ, 3 * SQ,
        a, (long long)SQ * HH, bnone, nullptr, nullptr, 0, 0, nullptr, 0.0f);

    // 4. O projection + residual -> x2 (fp32) and x2s (fp16 cvt)
    row_split3<<<(MT * HH / 4) / 256, blk>>>(a, as, HH);
    {
        PtrArr ba; ba.p[0] = bo;
        hmma_gemm<TE_BIAS_RESID_CVT1><<<dim3(HH / 128, MT / 128, 1), blk, HG_SMEM>>>(
            as, 0, wts + 3ULL * HH * HH * 3, 0, 3 * HH, x2, 0, ba, x, x2s, 0, HH,
            nullptr, 0.0f);
    }

    // 5. gates + output base
    gates_kernel<<<MT, 256>>>(x2, Wg, bg, g);
    out_init<<<(MT * HH / 4) / 256, blk>>>(x2, g, b2, out);

    // 6. expert up-proj (batched z=8, fp16)
    {
        PtrArr ba;
        for (int e = 0; e < 8; e++) ba.p[e] = b1 + (long long)e * DD;
        hmma_gemm<TE_BIAS_RELU_CVT1><<<dim3(DD / 128, MT / 128, EE), blk, HG_SMEM>>>(
            x2s, 0, w1ts, (long long)HH * DD, HH, nullptr, 0, ba, nullptr,
            hs, (long long)MT * DD, DD, nullptr, 0.0f);
    }

    // 7. expert down-proj (batched z=8, fp16) with fused gated accumulation
    hmma_gemm<TE_GATED_RED><<<dim3(HH / 128, MT / 128, EE), blk, HG_SMEM>>>(
        hs, (long long)MT * DD, w2ts, (long long)DD * HH, DD, out, 0, bnone,
        nullptr, nullptr, 0, 0, g, 0.0f);
}

// round 12
// speedup vs baseline: 5.8440x; 1.0911x over previous
#include <cuda_runtime.h>
#include <cuda_bf16.h>
#include <cuda_fp16.h>
#include <cstdint>

// ============================================================================
// TinyTransformerBlock on GB300 (compute_103 PTX -> HMMA fp16 tensor cores).
//  - QKV projection:  2-term split A'=[hi,lo] x B'=[hi,hi]  (= x * hi(W))
//  - Attention:       plain fp16 HMMA (q16,k16 fused out of QKV epilogue;
//                     probs fp16 fused out of softmax)
//  - O projection:    3-term split (protects residual trunk)
//  - MoE up/down:     plain fp16, gating fused via atomic RED.ADD
// fp32 accumulation in all HMMA. Softmax/gates fp32.
// ============================================================================

__device__ __forceinline__ uint32_t smem_to_u32(const void* p) {
    uint32_t a;
    asm("{ .reg .u64 t; cvta.to.shared.u64 t, %1; cvt.u32.u64 %0, t; }" : "=r"(a) : "l"(p));
    return a;
}
__device__ __forceinline__ void cp16(uint32_t saddr, const void* g) {
    asm volatile("cp.async.cg.shared.global [%0], [%1], 16;" :: "r"(saddr), "l"(g));
}
#define CP_COMMIT() asm volatile("cp.async.commit_group;" ::: "memory")
#define CP_WAIT_1() asm volatile("cp.async.wait_group 1;" ::: "memory")

__device__ __forceinline__ void ldm_x4(uint32_t* r, uint32_t addr) {
    asm volatile("ldmatrix.sync.aligned.m8n8.x4.shared.b16 {%0,%1,%2,%3}, [%4];"
        : "=r"(r[0]), "=r"(r[1]), "=r"(r[2]), "=r"(r[3]) : "r"(addr));
}
__device__ __forceinline__ void mma_16816(float* c, const uint32_t* a, uint32_t b0, uint32_t b1) {
    asm volatile("mma.sync.aligned.m16n8k16.row.col.f32.f16.f16.f32 "
        "{%0,%1,%2,%3}, {%4,%5,%6,%7}, {%8,%9}, {%0,%1,%2,%3};"
        : "+f"(c[0]), "+f"(c[1]), "+f"(c[2]), "+f"(c[3])
        : "r"(a[0]), "r"(a[1]), "r"(a[2]), "r"(a[3]), "r"(b0), "r"(b1));
}

// ---------------- problem sizes ----------------
#define MT 4096            // tokens
#define HH 1024            // hidden
#define DD 4096            // expert dim
#define EE 8               // experts
#define SQ 1024            // seq
#define BB 4               // batch

// ---------------- scratch (device globals; allocation-free) ----------------
__device__ __align__(1024) float g_qkv[3ULL * MT * HH];
__device__ __align__(1024) float g_s[(long long)BB * SQ * SQ];
__device__ __align__(1024) float g_a[(long long)MT * HH];
__device__ __align__(1024) float g_x2[(long long)MT * HH];
__device__ __align__(1024) float g_g[(long long)MT * EE];
__device__ __align__(1024) __half g_qkv16[3ULL * MT * HH];            // q16,k16 (v16 unused)
__device__ __align__(1024) __half g_xs2[(long long)MT * 2 * HH];      // x 2-term A-split
__device__ __align__(1024) __half g_as[(long long)MT * 3 * HH];       // a 3-term A-split
__device__ __align__(1024) __half g_ps[(long long)MT * SQ];           // probs fp16
__device__ __align__(1024) __half g_vts[(long long)BB * HH * SQ];     // V^T fp16
__device__ __align__(1024) __half g_x2s[(long long)MT * HH];          // x2 fp16
__device__ __align__(1024) __half g_wqkv2[3ULL * HH * 2 * HH];        // Wq,Wk,Wv 2-term B
__device__ __align__(1024) __half g_wo3[(long long)HH * 3 * HH];      // Wo 3-term B
__device__ __align__(1024) __half g_w1ts[(long long)EE * DD * HH];    // fp16 B
__device__ __align__(1024) __half g_w2ts[(long long)EE * HH * DD];    // fp16 B
__device__ __align__(1024) __half g_hs[(long long)EE * MT * DD];      // fp16 A

struct PtrArr { const float* p[8]; };

// A-side 3-term: [hi, lo, hi]
__device__ __forceinline__ void split3_pairA(float v0, float v1, __half* base,
                                             long long n, long long K) {
    __half h0 = __float2half_rn(v0), h1 = __float2half_rn(v1);
    __half l0 = __float2half_rn(v0 - __half2float(h0));
    __half l1 = __float2half_rn(v1 - __half2float(h1));
    __half2 hh = __halves2half2(h0, h1);
    __half2 ll = __halves2half2(l0, l1);
    *(__half2*)&base[n] = hh;
    *(__half2*)&base[K + n] = ll;
    *(__half2*)&base[2 * K + n] = hh;
}
// A-side 2-term: [hi, lo]
__device__ __forceinline__ void split2_pairA(float v0, float v1, __half* base,
                                             long long n, long long K) {
    __half h0 = __float2half_rn(v0), h1 = __float2half_rn(v1);
    __half l0 = __float2half_rn(v0 - __half2float(h0));
    __half l1 = __float2half_rn(v1 - __half2float(h1));
    *(__half2*)&base[n] = __halves2half2(h0, h1);
    *(__half2*)&base[K + n] = __halves2half2(l0, l1);
}

// ---------------- HMMA GEMM: C[M,N] = A'[M,K'] x B'[N,K']^T ----------------
// CTA 128x128, BK=64, 3-stage cp.async pipe, 8 warps (2M x 4N), warp 64x32.
enum { TE_BIAS_CVT1 = 0, TE_BIAS_RESID_CVT1 = 1, TE_BIAS_RELU_CVT1 = 2,
       TE_STORE = 3, TE_SCALE = 4, TE_GATED_RED = 5 };

#define HG_STAGE 32768          // A 16KB + B 16KB
#define HG_SMEM (3 * HG_STAGE)

__device__ __forceinline__ void load_tile_cp(uint32_t sbase, const __half* g,
                                             long long ld, int row0, int k0, int tid)
{
    const int r = tid >> 1;
    const int c0 = (tid & 1) * 4;
    const __half* gp = g + (long long)(row0 + r) * ld + k0 + c0 * 8;
    const uint32_t srow = sbase + r * 128;
#pragma unroll
    for (int i = 0; i < 4; i++)
        cp16(srow + (((c0 + i) ^ (r & 7)) << 4), gp + i * 8);
}

template <int EPI>
__global__ void __launch_bounds__(256)
hmma_gemm(const __half* __restrict__ A, long long aZ,
          const __half* __restrict__ B, long long bZ,
          int Kp, float* C, long long cZ, PtrArr bias, const float* resid,
          __half* cvt, long long cvtZ, int cvtK,
          const float* __restrict__ gate, float alpha)
{
    extern __shared__ __align__(1024) char smem[];
    const uint32_t sb = smem_to_u32(smem);
    const int tid = threadIdx.x;
    const int wid = tid >> 5, lane = tid & 31;
    const int z = blockIdx.z;
    const int m0 = blockIdx.y << 7;
    const int n0 = blockIdx.x << 7;
    const int Nt = gridDim.x << 7;
    const __half* Az = A + (long long)z * aZ;
    const __half* Bz = B + (long long)z * bZ;
    const int nch = Kp >> 6;

    const int wm = (wid >> 2) * 64;
    const int wn = (wid & 3) * 32;

    float acc[4][4][4];
#pragma unroll
    for (int i = 0; i < 4; i++)
#pragma unroll
        for (int j = 0; j < 4; j++)
#pragma unroll
            for (int r = 0; r < 4; r++) acc[i][j][r] = 0.0f;

    load_tile_cp(sb, Az, Kp, m0, 0, tid);
    load_tile_cp(sb + 16384, Bz, Kp, n0, 0, tid);
    CP_COMMIT();
    load_tile_cp(sb + HG_STAGE, Az, Kp, m0, 64, tid);
    load_tile_cp(sb + HG_STAGE + 16384, Bz, Kp, n0, 64, tid);
    CP_COMMIT();

    const int arow = lane & 15;
    const int ahalf = lane >> 4;
    const int brow = (lane & 7) + ((lane >> 4) & 1) * 8;
    const int bhalf = (lane >> 3) & 1;

    for (int c = 0; c < nch; c++) {
        CP_WAIT_1();
        __syncthreads();
        if (c + 2 < nch) {
            const uint32_t st = sb + ((c + 2) % 3) * HG_STAGE;
            load_tile_cp(st, Az, Kp, m0, (c + 2) * 64, tid);
            load_tile_cp(st + 16384, Bz, Kp, n0, (c + 2) * 64, tid);
        }
        CP_COMMIT();

        const uint32_t sA = sb + (c % 3) * HG_STAGE;
        const uint32_t sB = sA + 16384;
#pragma unroll
        for (int ks = 0; ks < 4; ks++) {
            uint32_t a[4][4];
#pragma unroll
            for (int mi = 0; mi < 4; mi++) {
                const int row = wm + mi * 16 + arow;
                const int ch = ks * 2 + ahalf;
                ldm_x4(a[mi], sA + row * 128 + ((ch ^ (row & 7)) << 4));
            }
            uint32_t b[2][4];
#pragma unroll
            for (int gI = 0; gI < 2; gI++) {
                const int row = wn + gI * 16 + brow;
                const int ch = ks * 2 + bhalf;
                ldm_x4(b[gI], sB + row * 128 + ((ch ^ (row & 7)) << 4));
            }
#pragma unroll
            for (int mi = 0; mi < 4; mi++)
#pragma unroll
                for (int ni = 0; ni < 4; ni++) {
                    const int gI = ni >> 1, off = (ni & 1) * 2;
                    mma_16816(acc[mi][ni], a[mi], b[gI][off], b[gI][off + 1]);
                }
        }
        __syncthreads();
    }

    // ---- epilogue ----
    const int l4 = lane >> 2, l2 = (lane & 3) << 1;
    float* Cz = C + (long long)z * cZ;
    const float* bz = bias.p[z];
    __half* cvz = (EPI == TE_BIAS_CVT1 || EPI == TE_BIAS_RESID_CVT1 ||
                   EPI == TE_BIAS_RELU_CVT1)
                      ? cvt + (long long)z * cvtZ : nullptr;

#pragma unroll
    for (int mi = 0; mi < 4; mi++)
#pragma unroll
        for (int h = 0; h < 2; h++) {
            const long long m = (long long)m0 + wm + mi * 16 + l4 + h * 8;
            float ge = 0.0f;
            if (EPI == TE_GATED_RED) ge = gate[m * EE + z];
#pragma unroll
            for (int ni = 0; ni < 4; ni++) {
                const long long n = n0 + wn + ni * 8 + l2;
                float v0 = acc[mi][ni][h * 2 + 0];
                float v1 = acc[mi][ni][h * 2 + 1];
                if (EPI == TE_BIAS_CVT1 || EPI == TE_BIAS_RESID_CVT1 ||
                    EPI == TE_BIAS_RELU_CVT1) {
                    v0 += bz[n]; v1 += bz[n + 1];
                }
                if (EPI == TE_SCALE) { v0 *= alpha; v1 *= alpha; }
                if (EPI == TE_BIAS_RELU_CVT1) {
                    v0 = fmaxf(v0, 0.0f); v1 = fmaxf(v1, 0.0f);
                }
                if (EPI == TE_BIAS_RESID_CVT1) {
                    float2 rv = *(const float2*)&resid[m * Nt + n];
                    v0 += rv.x; v1 += rv.y;
                }
                if (EPI == TE_BIAS_CVT1 || EPI == TE_STORE || EPI == TE_SCALE ||
                    EPI == TE_BIAS_RESID_CVT1) {
                    float2 o; o.x = v0; o.y = v1;
                    *(float2*)&Cz[m * Nt + n] = o;
                }
                if (EPI == TE_GATED_RED) {
                    atomicAdd(&Cz[m * Nt + n], ge * v0);
                    atomicAdd(&Cz[m * Nt + n + 1], ge * v1);
                }
                if (EPI == TE_BIAS_CVT1 || EPI == TE_BIAS_RESID_CVT1 ||
                    EPI == TE_BIAS_RELU_CVT1) {
                    *(__half2*)&cvz[m * cvtK + n] =
                        __halves2half2(__float2half_rn(v0), __float2half_rn(v1));
                }
            }
        }
}

// ---------------- split helpers ----------------
// A-side 3-term row split: [M,K] fp32 -> [M,3K] fp16 [hi, lo, hi]
__global__ void row_split3(const float* __restrict__ in, __half* __restrict__ out, int K)
{
    const long long i = (long long)blockIdx.x * blockDim.x + threadIdx.x;
    const int K4 = K >> 2;
    const long long mrow = i / K4;
    const int k4 = (int)(i % K4) << 2;
    float4 v = *(const float4*)&in[mrow * K + k4];
    __half* o = out + mrow * (3LL * K);
    split3_pairA(v.x, v.y, o, k4, K);
    split3_pairA(v.z, v.w, o, k4 + 2, K);
}
// A-side 2-term row split: [M,K] fp32 -> [M,2K] fp16 [hi, lo]
__global__ void row_split2(const float* __restrict__ in, __half* __restrict__ out, int K)
{
    const long long i = (long long)blockIdx.x * blockDim.x + threadIdx.x;
    const int K4 = K >> 2;
    const long long mrow = i / K4;
    const int k4 = (int)(i % K4) << 2;
    float4 v = *(const float4*)&in[mrow * K + k4];
    __half* o = out + mrow * (2LL * K);
    split2_pairA(v.x, v.y, o, k4, K);
    split2_pairA(v.z, v.w, o, k4 + 2, K);
}

// B-side transpose split: in [K,N] fp32 -> out [N, TERMS*K] fp16
// TERMS==3: [hi, hi, lo]; TERMS==2: [hi, hi]; TERMS==1: [hi]
// __half2 stores (coalesced 128B per warp).
template <int TERMS>
__global__ void transpose_split(PtrArr in, int K, int N,
                                __half* __restrict__ out, long long outZ)
{
    __shared__ float t[64][65];
    const float* src = in.p[blockIdx.z];
    __half* dst = out + blockIdx.z * outZ;
    const int n0 = blockIdx.x * 64, k0 = blockIdx.y * 64;
    const int tr = threadIdx.x >> 6;      // 0..3
    const int tc = threadIdx.x & 63;      // 0..63
#pragma unroll
    for (int j = 0; j < 16; j++) {
        const int r = tr + j * 4;
        t[r][tc] = src[(long long)(k0 + r) * N + n0 + tc];
    }
    __syncthreads();
    const int sr = threadIdx.x >> 5;      // 0..7
    const int c = threadIdx.x & 31;       // 0..31 -> k pair
#pragma unroll
    for (int j = 0; j < 8; j++) {
        const int rn = sr + j * 8;        // local n row
        const float v0 = t[2 * c][rn];
        const float v1 = t[2 * c + 1][rn];
        const __half h0 = __float2half_rn(v0);
        const __half h1 = __float2half_rn(v1);
        const __half2 hh = __halves2half2(h0, h1);
        __half* o = dst + (long long)(n0 + rn) * ((long long)TERMS * K) + k0 + 2 * c;
        *(__half2*)&o[0] = hh;
        if (TERMS >= 2) *(__half2*)&o[K] = hh;
        if (TERMS == 3) {
            const __half2 ll = __halves2half2(
                __float2half_rn(v0 - __half2float(h0)),
                __float2half_rn(v1 - __half2float(h1)));
            *(__half2*)&o[2LL * K] = ll;
        }
    }
}

// softmax over rows; fp32 in/out scratch S, fp16 probs out P
__global__ void softmax_rows(float* __restrict__ S, __half* __restrict__ P, int ncols)
{
    const int row = blockIdx.x;
    float* p = S + (long long)row * ncols;
    __half* q = P + (long long)row * ncols;
    const int tid = threadIdx.x;
    __shared__ float red[256];
    float m = -1e30f;
    for (int c = tid; c < ncols; c += 256) m = fmaxf(m, p[c]);
    red[tid] = m; __syncthreads();
    for (int s = 128; s > 0; s >>= 1) { if (tid < s) red[tid] = fmaxf(red[tid], red[tid + s]); __syncthreads(); }
    m = red[0]; __syncthreads();
    float sum = 0.0f;
    for (int c = tid; c < ncols; c += 256) { float e = __expf(p[c] - m); p[c] = e; sum += e; }
    red[tid] = sum; __syncthreads();
    for (int s = 128; s > 0; s >>= 1) { if (tid < s) red[tid] += red[tid + s]; __syncthreads(); }
    const float inv = 1.0f / red[0];
    for (int c = tid; c < ncols; c += 256) q[c] = __float2half_rn(p[c] * inv);
}

__global__ void gates_kernel(const float* __restrict__ x2, const float* __restrict__ Wg,
                             const float* __restrict__ bg, float* __restrict__ G)
{
    const int row = blockIdx.x;
    const int tid = threadIdx.x;
    const float* xp = x2 + (long long)row * HH;
    float part[8];
#pragma unroll
    for (int e = 0; e < 8; e++) part[e] = 0.0f;
    for (int h = tid; h < HH; h += 256) {
        float xv = xp[h];
#pragma unroll
        for (int e = 0; e < 8; e++) part[e] = fmaf(xv, Wg[h * 8 + e], part[e]);
    }
    __shared__ float red[256];
    __shared__ float logits[8];
#pragma unroll
    for (int e = 0; e < 8; e++) {
        red[tid] = part[e]; __syncthreads();
        for (int s = 128; s > 0; s >>= 1) { if (tid < s) red[tid] += red[tid + s]; __syncthreads(); }
        if (tid == 0) logits[e] = red[0] + bg[e];
        __syncthreads();
    }
    if (tid == 0) {
        float m = -1e30f;
#pragma unroll
        for (int e = 0; e < 8; e++) m = fmaxf(m, logits[e]);
        float ex[8], s = 0.0f;
#pragma unroll
        for (int e = 0; e < 8; e++) { ex[e] = __expf(logits[e] - m); s += ex[e]; }
        const float inv = 1.0f / s;
#pragma unroll
        for (int e = 0; e < 8; e++) G[row * 8 + e] = ex[e] * inv;
    }
}

// out[m,n] = x2[m,n] + sum_e g[m,e] * b2[e][n]   (base for gated RED accumulation)
__global__ void out_init(const float* __restrict__ x2, const float* __restrict__ g,
                         const float* __restrict__ b2, float* __restrict__ out)
{
    const long long i = (long long)blockIdx.x * blockDim.x + threadIdx.x;
    const long long m = i / (HH / 4);
    const int n4 = (int)(i % (HH / 4)) << 2;
    float4 acc = *(const float4*)&x2[m * HH + n4];
#pragma unroll
    for (int e = 0; e < 8; e++) {
        const float ge = g[m * 8 + e];
        float4 b = *(const float4*)&b2[e * HH + n4];
        acc.x += ge * b.x; acc.y += ge * b.y;
        acc.z += ge * b.z; acc.w += ge * b.w;
    }
    *(float4*)&out[m * HH + n4] = acc;
}

// ---------------- host side ----------------
extern "C" void kernel_launch(void* const* d_in, const int* in_sizes, int n_in,
                              void* d_out, int out_size)
{
    const float* x  = (const float*)d_in[0];
    const float* Wq = (const float*)d_in[1];
    const float* bq = (const float*)d_in[2];
    const float* Wk = (const float*)d_in[3];
    const float* bk = (const float*)d_in[4];
    const float* Wv = (const float*)d_in[5];
    const float* bv = (const float*)d_in[6];
    const float* Wo = (const float*)d_in[7];
    const float* bo = (const float*)d_in[8];
    const float* Wg = (const float*)d_in[9];
    const float* bg = (const float*)d_in[10];
    const float* W1 = (const float*)d_in[11];
    const float* b1 = (const float*)d_in[12];
    const float* W2 = (const float*)d_in[13];
    const float* b2 = (const float*)d_in[14];
    float* out = (float*)d_out;

    float *qkv, *s, *a, *x2, *g;
    __half *qkv16, *xs2, *as, *ps, *vts, *x2s, *wqkv2, *wo3, *w1ts, *w2ts, *hs;
    cudaGetSymbolAddress((void**)&qkv, g_qkv);
    cudaGetSymbolAddress((void**)&s, g_s);
    cudaGetSymbolAddress((void**)&a, g_a);
    cudaGetSymbolAddress((void**)&x2, g_x2);
    cudaGetSymbolAddress((void**)&g, g_g);
    cudaGetSymbolAddress((void**)&qkv16, g_qkv16);
    cudaGetSymbolAddress((void**)&xs2, g_xs2);
    cudaGetSymbolAddress((void**)&as, g_as);
    cudaGetSymbolAddress((void**)&ps, g_ps);
    cudaGetSymbolAddress((void**)&vts, g_vts);
    cudaGetSymbolAddress((void**)&x2s, g_x2s);
    cudaGetSymbolAddress((void**)&wqkv2, g_wqkv2);
    cudaGetSymbolAddress((void**)&wo3, g_wo3);
    cudaGetSymbolAddress((void**)&w1ts, g_w1ts);
    cudaGetSymbolAddress((void**)&w2ts, g_w2ts);
    cudaGetSymbolAddress((void**)&hs, g_hs);

    cudaFuncSetAttribute(hmma_gemm<TE_BIAS_CVT1>, cudaFuncAttributeMaxDynamicSharedMemorySize, HG_SMEM);
    cudaFuncSetAttribute(hmma_gemm<TE_BIAS_RESID_CVT1>, cudaFuncAttributeMaxDynamicSharedMemorySize, HG_SMEM);
    cudaFuncSetAttribute(hmma_gemm<TE_BIAS_RELU_CVT1>, cudaFuncAttributeMaxDynamicSharedMemorySize, HG_SMEM);
    cudaFuncSetAttribute(hmma_gemm<TE_STORE>, cudaFuncAttributeMaxDynamicSharedMemorySize, HG_SMEM);
    cudaFuncSetAttribute(hmma_gemm<TE_SCALE>, cudaFuncAttributeMaxDynamicSharedMemorySize, HG_SMEM);
    cudaFuncSetAttribute(hmma_gemm<TE_GATED_RED>, cudaFuncAttributeMaxDynamicSharedMemorySize, HG_SMEM);

    PtrArr bnone = {};
    dim3 blk(256);

    // 1. splits of inputs / weights
    row_split2<<<(MT * HH / 4) / 256, blk>>>(x, xs2, HH);
    {
        PtrArr wi; wi.p[0] = Wq; wi.p[1] = Wk; wi.p[2] = Wv;
        transpose_split<2><<<dim3(HH / 64, HH / 64, 3), blk>>>(wi, HH, HH, wqkv2, 2LL * HH * HH);
    }
    {
        PtrArr wi; wi.p[0] = Wo;
        transpose_split<3><<<dim3(HH / 64, HH / 64, 1), blk>>>(wi, HH, HH, wo3, 0);
    }
    {
        PtrArr wi;
        for (int e = 0; e < 8; e++) wi.p[e] = W1 + (long long)e * HH * DD;
        transpose_split<1><<<dim3(DD / 64, HH / 64, EE), blk>>>(wi, HH, DD, w1ts, (long long)HH * DD);
    }
    {
        PtrArr wi;
        for (int e = 0; e < 8; e++) wi.p[e] = W2 + (long long)e * DD * HH;
        transpose_split<1><<<dim3(HH / 64, DD / 64, EE), blk>>>(wi, DD, HH, w2ts, (long long)DD * HH);
    }

    // 2. QKV projections (batched z=3, 2-term) + fused fp16 cvt (q16,k16)
    {
        PtrArr ba; ba.p[0] = bq; ba.p[1] = bk; ba.p[2] = bv;
        hmma_gemm<TE_BIAS_CVT1><<<dim3(HH / 128, MT / 128, 3), blk, HG_SMEM>>>(
            xs2, 0, wqkv2, 2LL * HH * HH, 2 * HH, qkv, (long long)MT * HH, ba,
            nullptr, qkv16, (long long)MT * HH, HH, nullptr, 0.0f);
    }
    const __half* q16 = qkv16;
    const __half* k16 = qkv16 + (long long)MT * HH;
    const float* v = qkv + 2LL * MT * HH;

    // 3. attention core (plain fp16 HMMA)
    hmma_gemm<TE_SCALE><<<dim3(SQ / 128, SQ / 128, BB), blk, HG_SMEM>>>(
        q16, (long long)SQ * HH, k16, (long long)SQ * HH, HH,
        s, (long long)SQ * SQ, bnone, nullptr, nullptr, 0, 0, nullptr, 0.03125f);
    softmax_rows<<<BB * SQ, 256>>>(s, ps, SQ);
    {
        PtrArr vi;
        for (int b = 0; b < BB; b++) vi.p[b] = v + (long long)b * SQ * HH;
        transpose_split<1><<<dim3(HH / 64, SQ / 64, BB), blk>>>(vi, SQ, HH, vts, (long long)HH * SQ);
    }
    hmma_gemm<TE_STORE><<<dim3(HH / 128, SQ / 128, BB), blk, HG_SMEM>>>(
        ps, (long long)SQ * SQ, vts, (long long)HH * SQ, SQ,
        a, (long long)SQ * HH, bnone, nullptr, nullptr, 0, 0, nullptr, 0.0f);

    // 4. O projection (3-term) + residual -> x2 (fp32) and x2s (fp16 cvt)
    row_split3<<<(MT * HH / 4) / 256, blk>>>(a, as, HH);
    {
        PtrArr ba; ba.p[0] = bo;
        hmma_gemm<TE_BIAS_RESID_CVT1><<<dim3(HH / 128, MT / 128, 1), blk, HG_SMEM>>>(
            as, 0, wo3, 0, 3 * HH, x2, 0, ba, x, x2s, 0, HH, nullptr, 0.0f);
    }

    // 5. gates + output base
    gates_kernel<<<MT, 256>>>(x2, Wg, bg, g);
    out_init<<<(MT * HH / 4) / 256, blk>>>(x2, g, b2, out);

    // 6. expert up-proj (batched z=8, fp16)
    {
        PtrArr ba;
        for (int e = 0; e < 8; e++) ba.p[e] = b1 + (long long)e * DD;
        hmma_gemm<TE_BIAS_RELU_CVT1><<<dim3(DD / 128, MT / 128, EE), blk, HG_SMEM>>>(
            x2s, 0, w1ts, (long long)HH * DD, HH, nullptr, 0, ba, nullptr,
            hs, (long long)MT * DD, DD, nullptr, 0.0f);
    }

    // 7. expert down-proj (batched z=8, fp16) with fused gated accumulation
    hmma_gemm<TE_GATED_RED><<<dim3(HH / 128, MT / 128, EE), blk, HG_SMEM>>>(
        hs, (long long)MT * DD, w2ts, (long long)DD * HH, DD, out, 0, bnone,
        nullptr, nullptr, 0, 0, g, 0.0f);
}

// round 13
// speedup vs baseline: 6.2020x; 1.0613x over previous
#include <cuda_runtime.h>
#include <cuda_bf16.h>
#include <cuda_fp16.h>
#include <cstdint>

// ============================================================================
// TinyTransformerBlock on GB300 (compute_103 PTX -> HMMA fp16 tensor cores).
//  - QKV projection:  1-term fp16 (q,k,v all consumed as fp16 downstream)
//  - Attention:       plain fp16 HMMA; fp32 scores; reg-resident softmax
//  - O projection:    2-term split (a's own error already ~3e-4-scale)
//  - MoE up/down:     plain fp16, gating fused via atomic RED.ADD
// fp32 accumulation in all HMMA. Softmax/gates fp32.
// ============================================================================

__device__ __forceinline__ uint32_t smem_to_u32(const void* p) {
    uint32_t a;
    asm("{ .reg .u64 t; cvta.to.shared.u64 t, %1; cvt.u32.u64 %0, t; }" : "=r"(a) : "l"(p));
    return a;
}
__device__ __forceinline__ void cp16(uint32_t saddr, const void* g) {
    asm volatile("cp.async.cg.shared.global [%0], [%1], 16;" :: "r"(saddr), "l"(g));
}
#define CP_COMMIT() asm volatile("cp.async.commit_group;" ::: "memory")
#define CP_WAIT_1() asm volatile("cp.async.wait_group 1;" ::: "memory")

__device__ __forceinline__ void ldm_x4(uint32_t* r, uint32_t addr) {
    asm volatile("ldmatrix.sync.aligned.m8n8.x4.shared.b16 {%0,%1,%2,%3}, [%4];"
        : "=r"(r[0]), "=r"(r[1]), "=r"(r[2]), "=r"(r[3]) : "r"(addr));
}
__device__ __forceinline__ void mma_16816(float* c, const uint32_t* a, uint32_t b0, uint32_t b1) {
    asm volatile("mma.sync.aligned.m16n8k16.row.col.f32.f16.f16.f32 "
        "{%0,%1,%2,%3}, {%4,%5,%6,%7}, {%8,%9}, {%0,%1,%2,%3};"
        : "+f"(c[0]), "+f"(c[1]), "+f"(c[2]), "+f"(c[3])
        : "r"(a[0]), "r"(a[1]), "r"(a[2]), "r"(a[3]), "r"(b0), "r"(b1));
}

// ---------------- problem sizes ----------------
#define MT 4096
#define HH 1024
#define DD 4096
#define EE 8
#define SQ 1024
#define BB 4

// ---------------- scratch (device globals; allocation-free) ----------------
__device__ __align__(1024) float g_s[(long long)BB * SQ * SQ];        // fp32 scores
__device__ __align__(1024) float g_x2[(long long)MT * HH];
__device__ __align__(1024) float g_g[(long long)MT * EE];
__device__ __align__(1024) __half g_x16[(long long)MT * HH];          // x fp16
__device__ __align__(1024) __half g_qkv16[3ULL * MT * HH];            // q16,k16,v16
__device__ __align__(1024) __half g_ps[(long long)MT * SQ];           // probs fp16
__device__ __align__(1024) __half g_vts[(long long)BB * HH * SQ];     // V^T fp16
__device__ __align__(1024) __half g_as2[(long long)MT * 2 * HH];      // a 2-term split
__device__ __align__(1024) __half g_x2s[(long long)MT * HH];          // x2 fp16
__device__ __align__(1024) __half g_wqkv1[3ULL * HH * HH];            // 1-term B
__device__ __align__(1024) __half g_wo2[(long long)HH * 2 * HH];      // Wo 2-term B
__device__ __align__(1024) __half g_w1ts[(long long)EE * DD * HH];
__device__ __align__(1024) __half g_w2ts[(long long)EE * HH * DD];
__device__ __align__(1024) __half g_hs[(long long)EE * MT * DD];

struct PtrArr { const float* p[8]; };

// ---------------- HMMA GEMM ----------------
enum { TE_BIAS_CVT16 = 0,      // bias, fp16 store only (QKV)
       TE_SCALE = 1,           // *alpha, fp32 store (scores)
       TE_SPLIT2 = 2,          // raw acc -> [hi|lo] fp16 split store (a)
       TE_BIAS_RESID_CVT1 = 3, // bias+resid, fp32 + fp16 store (x2)
       TE_BIAS_RELU_CVT16 = 4, // bias+relu, fp16 store (hs)
       TE_GATED_RED = 5 };     // gate*acc atomically into out

#define HG_STAGE 32768
#define HG_SMEM (3 * HG_STAGE)

__device__ __forceinline__ void load_tile_cp(uint32_t sbase, const __half* g,
                                             long long ld, int row0, int k0, int tid)
{
    const int r = tid >> 1;
    const int c0 = (tid & 1) * 4;
    const __half* gp = g + (long long)(row0 + r) * ld + k0 + c0 * 8;
    const uint32_t srow = sbase + r * 128;
#pragma unroll
    for (int i = 0; i < 4; i++)
        cp16(srow + (((c0 + i) ^ (r & 7)) << 4), gp + i * 8);
}

template <int EPI>
__global__ void __launch_bounds__(256)
hmma_gemm(const __half* __restrict__ A, long long aZ,
          const __half* __restrict__ B, long long bZ,
          int Kp, float* C, long long cZ, PtrArr bias, const float* resid,
          __half* cvt, long long cvtZ, int cvtK,
          const float* __restrict__ gate, float alpha)
{
    extern __shared__ __align__(1024) char smem[];
    const uint32_t sb = smem_to_u32(smem);
    const int tid = threadIdx.x;
    const int wid = tid >> 5, lane = tid & 31;
    const int z = blockIdx.z;
    const int m0 = blockIdx.y << 7;
    const int n0 = blockIdx.x << 7;
    const int Nt = gridDim.x << 7;
    const __half* Az = A + (long long)z * aZ;
    const __half* Bz = B + (long long)z * bZ;
    const int nch = Kp >> 6;

    const int wm = (wid >> 2) * 64;
    const int wn = (wid & 3) * 32;

    float acc[4][4][4];
#pragma unroll
    for (int i = 0; i < 4; i++)
#pragma unroll
        for (int j = 0; j < 4; j++)
#pragma unroll
            for (int r = 0; r < 4; r++) acc[i][j][r] = 0.0f;

    load_tile_cp(sb, Az, Kp, m0, 0, tid);
    load_tile_cp(sb + 16384, Bz, Kp, n0, 0, tid);
    CP_COMMIT();
    load_tile_cp(sb + HG_STAGE, Az, Kp, m0, 64, tid);
    load_tile_cp(sb + HG_STAGE + 16384, Bz, Kp, n0, 64, tid);
    CP_COMMIT();

    const int arow = lane & 15;
    const int ahalf = lane >> 4;
    const int brow = (lane & 7) + ((lane >> 4) & 1) * 8;
    const int bhalf = (lane >> 3) & 1;

    for (int c = 0; c < nch; c++) {
        CP_WAIT_1();
        __syncthreads();
        if (c + 2 < nch) {
            const uint32_t st = sb + ((c + 2) % 3) * HG_STAGE;
            load_tile_cp(st, Az, Kp, m0, (c + 2) * 64, tid);
            load_tile_cp(st + 16384, Bz, Kp, n0, (c + 2) * 64, tid);
        }
        CP_COMMIT();

        const uint32_t sA = sb + (c % 3) * HG_STAGE;
        const uint32_t sB = sA + 16384;
#pragma unroll
        for (int ks = 0; ks < 4; ks++) {
            uint32_t a[4][4];
#pragma unroll
            for (int mi = 0; mi < 4; mi++) {
                const int row = wm + mi * 16 + arow;
                const int ch = ks * 2 + ahalf;
                ldm_x4(a[mi], sA + row * 128 + ((ch ^ (row & 7)) << 4));
            }
            uint32_t b[2][4];
#pragma unroll
            for (int gI = 0; gI < 2; gI++) {
                const int row = wn + gI * 16 + brow;
                const int ch = ks * 2 + bhalf;
                ldm_x4(b[gI], sB + row * 128 + ((ch ^ (row & 7)) << 4));
            }
#pragma unroll
            for (int mi = 0; mi < 4; mi++)
#pragma unroll
                for (int ni = 0; ni < 4; ni++) {
                    const int gI = ni >> 1, off = (ni & 1) * 2;
                    mma_16816(acc[mi][ni], a[mi], b[gI][off], b[gI][off + 1]);
                }
        }
        __syncthreads();
    }

    // ---- epilogue ----
    const int l4 = lane >> 2, l2 = (lane & 3) << 1;
    float* Cz = C ? C + (long long)z * cZ : nullptr;
    const float* bz = bias.p[z];
    __half* cvz = cvt ? cvt + (long long)z * cvtZ : nullptr;

#pragma unroll
    for (int mi = 0; mi < 4; mi++)
#pragma unroll
        for (int h = 0; h < 2; h++) {
            const long long m = (long long)m0 + wm + mi * 16 + l4 + h * 8;
            float ge = 0.0f;
            if (EPI == TE_GATED_RED) ge = gate[m * EE + z];
#pragma unroll
            for (int ni = 0; ni < 4; ni++) {
                const long long n = n0 + wn + ni * 8 + l2;
                float v0 = acc[mi][ni][h * 2 + 0];
                float v1 = acc[mi][ni][h * 2 + 1];
                if (EPI == TE_BIAS_CVT16 || EPI == TE_BIAS_RESID_CVT1 ||
                    EPI == TE_BIAS_RELU_CVT16) {
                    v0 += bz[n]; v1 += bz[n + 1];
                }
                if (EPI == TE_SCALE) { v0 *= alpha; v1 *= alpha; }
                if (EPI == TE_BIAS_RELU_CVT16) {
                    v0 = fmaxf(v0, 0.0f); v1 = fmaxf(v1, 0.0f);
                }
                if (EPI == TE_BIAS_RESID_CVT1) {
                    float2 rv = *(const float2*)&resid[m * Nt + n];
                    v0 += rv.x; v1 += rv.y;
                }
                if (EPI == TE_SCALE || EPI == TE_BIAS_RESID_CVT1) {
                    float2 o; o.x = v0; o.y = v1;
                    *(float2*)&Cz[m * Nt + n] = o;
                }
                if (EPI == TE_GATED_RED) {
                    atomicAdd(&Cz[m * Nt + n], ge * v0);
                    atomicAdd(&Cz[m * Nt + n + 1], ge * v1);
                }
                if (EPI == TE_BIAS_CVT16 || EPI == TE_BIAS_RESID_CVT1 ||
                    EPI == TE_BIAS_RELU_CVT16) {
                    *(__half2*)&cvz[m * cvtK + n] =
                        __halves2half2(__float2half_rn(v0), __float2half_rn(v1));
                }
                if (EPI == TE_SPLIT2) {
                    __half h0 = __float2half_rn(v0), h1 = __float2half_rn(v1);
                    __half l0 = __float2half_rn(v0 - __half2float(h0));
                    __half l1 = __float2half_rn(v1 - __half2float(h1));
                    __half* o = cvz + m * (2LL * cvtK) + n;
                    *(__half2*)&o[0] = __halves2half2(h0, h1);
                    *(__half2*)&o[cvtK] = __halves2half2(l0, l1);
                }
            }
        }
}

// ---------------- aux kernels ----------------
// plain fp32 -> fp16 streaming convert
__global__ void cvt16(const float* __restrict__ in, __half* __restrict__ out)
{
    const long long i = (long long)blockIdx.x * blockDim.x + threadIdx.x;
    float4 v = ((const float4*)in)[i];
    __half2 a = __floats2half2_rn(v.x, v.y);
    __half2 b = __floats2half2_rn(v.z, v.w);
    uint2 u; u.x = *(uint32_t*)&a; u.y = *(uint32_t*)&b;
    ((uint2*)out)[i] = u;
}

// B-side transpose split: in [K,N] fp32 -> out [N, TERMS*K] fp16
// TERMS==2: [hi, hi]; TERMS==1: [hi].  float4 loads, uint2 stores.
template <int TERMS>
__global__ void transpose_split(PtrArr in, int K, int N,
                                __half* __restrict__ out, long long outZ)
{
    __shared__ float t[64][65];
    const float* src = in.p[blockIdx.z];
    __half* dst = out + blockIdx.z * outZ;
    const int n0 = blockIdx.x * 64, k0 = blockIdx.y * 64;
    const int lr = threadIdx.x >> 4;          // 0..15
    const int lc = (threadIdx.x & 15) * 4;    // 0..60
#pragma unroll
    for (int j = 0; j < 4; j++) {
        const int r = lr + j * 16;
        float4 v = *(const float4*)&src[(long long)(k0 + r) * N + n0 + lc];
        t[r][lc] = v.x; t[r][lc + 1] = v.y; t[r][lc + 2] = v.z; t[r][lc + 3] = v.w;
    }
    __syncthreads();
    const int orow = threadIdx.x >> 2;        // 0..63 (n)
    const int oc = threadIdx.x & 3;
    __half* obase = dst + (long long)(n0 + orow) * ((long long)TERMS * K) + k0;
#pragma unroll
    for (int j = 0; j < 4; j++) {
        const int kq = (oc + j * 4) * 4;
        const float v0 = t[kq][orow], v1 = t[kq + 1][orow];
        const float v2 = t[kq + 2][orow], v3 = t[kq + 3][orow];
        __half2 a = __floats2half2_rn(v0, v1);
        __half2 b = __floats2half2_rn(v2, v3);
        uint2 u; u.x = *(uint32_t*)&a; u.y = *(uint32_t*)&b;
        *(uint2*)&obase[kq] = u;
        if (TERMS == 2) *(uint2*)&obase[K + kq] = u;
    }
}

// fp16 transpose: in [K,N] -> out [N,K]
__global__ void transpose_h(const __half* __restrict__ in, long long inZ,
                            __half* __restrict__ out, long long outZ, int K, int N)
{
    __shared__ __half t[64][66];
    const __half* src = in + blockIdx.z * inZ;
    __half* dst = out + blockIdx.z * outZ;
    const int n0 = blockIdx.x * 64, k0 = blockIdx.y * 64;
    const int lr = threadIdx.x >> 4;
    const int lc = (threadIdx.x & 15) * 4;
#pragma unroll
    for (int j = 0; j < 4; j++) {
        const int r = lr + j * 16;
        uint2 v = *(const uint2*)&src[(long long)(k0 + r) * N + n0 + lc];
        *(__half2*)&t[r][lc] = *(__half2*)&v.x;
        *(__half2*)&t[r][lc + 2] = *(__half2*)&v.y;
    }
    __syncthreads();
    const int orow = threadIdx.x >> 2;
    const int oc = threadIdx.x & 3;
    __half* obase = dst + (long long)(n0 + orow) * K + k0;
#pragma unroll
    for (int j = 0; j < 4; j++) {
        const int kq = (oc + j * 4) * 4;
        __half2 a = __halves2half2(t[kq][orow], t[kq + 1][orow]);
        __half2 b = __halves2half2(t[kq + 2][orow], t[kq + 3][orow]);
        uint2 u; u.x = *(uint32_t*)&a; u.y = *(uint32_t*)&b;
        *(uint2*)&obase[kq] = u;
    }
}

// register-resident softmax: 1024 cols, 256 threads, 4 vals/thread; fp16 out
__global__ void softmax_rows(const float* __restrict__ S, __half* __restrict__ P)
{
    const int row = blockIdx.x, tid = threadIdx.x;
    float4 v = ((const float4*)(S + (long long)row * SQ))[tid];
    __shared__ float red[256];
    float m = fmaxf(fmaxf(v.x, v.y), fmaxf(v.z, v.w));
    red[tid] = m; __syncthreads();
    for (int s = 128; s > 0; s >>= 1) {
        if (tid < s) red[tid] = fmaxf(red[tid], red[tid + s]);
        __syncthreads();
    }
    m = red[0]; __syncthreads();
    float e0 = __expf(v.x - m), e1 = __expf(v.y - m);
    float e2 = __expf(v.z - m), e3 = __expf(v.w - m);
    red[tid] = e0 + e1 + e2 + e3; __syncthreads();
    for (int s = 128; s > 0; s >>= 1) {
        if (tid < s) red[tid] += red[tid + s];
        __syncthreads();
    }
    const float inv = 1.0f / red[0];
    __half2 a = __floats2half2_rn(e0 * inv, e1 * inv);
    __half2 b = __floats2half2_rn(e2 * inv, e3 * inv);
    uint2 u; u.x = *(uint32_t*)&a; u.y = *(uint32_t*)&b;
    ((uint2*)(P + (long long)row * SQ))[tid] = u;
}

// fused gates + output base: G[row] = softmax(x2@Wg+bg);
// out[row] = x2[row] + sum_e G[e]*b2[e]
__global__ void gates_out(const float* __restrict__ x2, const float* __restrict__ Wg,
                          const float* __restrict__ bg, const float* __restrict__ b2,
                          float* __restrict__ G, float* __restrict__ out)
{
    const int row = blockIdx.x, tid = threadIdx.x;
    float4 xv = ((const float4*)(x2 + (long long)row * HH))[tid];
    float xa[4] = {xv.x, xv.y, xv.z, xv.w};
    float part[8];
#pragma unroll
    for (int e = 0; e < 8; e++) part[e] = 0.0f;
    const float* w = Wg + (long long)tid * 4 * 8;
#pragma unroll
    for (int i = 0; i < 4; i++)
#pragma unroll
        for (int e = 0; e < 8; e++)
            part[e] = fmaf(xa[i], w[i * 8 + e], part[e]);

    __shared__ float red[256];
    __shared__ float gsh[8];
#pragma unroll
    for (int e = 0; e < 8; e++) {
        red[tid] = part[e]; __syncthreads();
        for (int s = 128; s > 0; s >>= 1) {
            if (tid < s) red[tid] += red[tid + s];
            __syncthreads();
        }
        if (tid == 0) gsh[e] = red[0] + bg[e];
        __syncthreads();
    }
    if (tid == 0) {
        float m = -1e30f;
#pragma unroll
        for (int e = 0; e < 8; e++) m = fmaxf(m, gsh[e]);
        float ex[8], s = 0.0f;
#pragma unroll
        for (int e = 0; e < 8; e++) { ex[e] = __expf(gsh[e] - m); s += ex[e]; }
        const float inv = 1.0f / s;
#pragma unroll
        for (int e = 0; e < 8; e++) { gsh[e] = ex[e] * inv; G[row * 8 + e] = gsh[e]; }
    }
    __syncthreads();
    float4 acc = xv;
#pragma unroll
    for (int e = 0; e < 8; e++) {
        const float ge = gsh[e];
        float4 b = ((const float4*)(b2 + e * HH))[tid];
        acc.x = fmaf(ge, b.x, acc.x); acc.y = fmaf(ge, b.y, acc.y);
        acc.z = fmaf(ge, b.z, acc.z); acc.w = fmaf(ge, b.w, acc.w);
    }
    ((float4*)(out + (long long)row * HH))[tid] = acc;
}

// ---------------- host side ----------------
extern "C" void kernel_launch(void* const* d_in, const int* in_sizes, int n_in,
                              void* d_out, int out_size)
{
    const float* x  = (const float*)d_in[0];
    const float* Wq = (const float*)d_in[1];
    const float* bq = (const float*)d_in[2];
    const float* Wk = (const float*)d_in[3];
    const float* bk = (const float*)d_in[4];
    const float* Wv = (const float*)d_in[5];
    const float* bv = (const float*)d_in[6];
    const float* Wo = (const float*)d_in[7];
    const float* bo = (const float*)d_in[8];
    const float* Wg = (const float*)d_in[9];
    const float* bg = (const float*)d_in[10];
    const float* W1 = (const float*)d_in[11];
    const float* b1 = (const float*)d_in[12];
    const float* W2 = (const float*)d_in[13];
    const float* b2 = (const float*)d_in[14];
    float* out = (float*)d_out;

    float *s, *x2, *g;
    __half *x16, *qkv16, *ps, *vts, *as2, *x2s, *wqkv1, *wo2, *w1ts, *w2ts, *hs;
    cudaGetSymbolAddress((void**)&s, g_s);
    cudaGetSymbolAddress((void**)&x2, g_x2);
    cudaGetSymbolAddress((void**)&g, g_g);
    cudaGetSymbolAddress((void**)&x16, g_x16);
    cudaGetSymbolAddress((void**)&qkv16, g_qkv16);
    cudaGetSymbolAddress((void**)&ps, g_ps);
    cudaGetSymbolAddress((void**)&vts, g_vts);
    cudaGetSymbolAddress((void**)&as2, g_as2);
    cudaGetSymbolAddress((void**)&x2s, g_x2s);
    cudaGetSymbolAddress((void**)&wqkv1, g_wqkv1);
    cudaGetSymbolAddress((void**)&wo2, g_wo2);
    cudaGetSymbolAddress((void**)&w1ts, g_w1ts);
    cudaGetSymbolAddress((void**)&w2ts, g_w2ts);
    cudaGetSymbolAddress((void**)&hs, g_hs);

    cudaFuncSetAttribute(hmma_gemm<TE_BIAS_CVT16>, cudaFuncAttributeMaxDynamicSharedMemorySize, HG_SMEM);
    cudaFuncSetAttribute(hmma_gemm<TE_SCALE>, cudaFuncAttributeMaxDynamicSharedMemorySize, HG_SMEM);
    cudaFuncSetAttribute(hmma_gemm<TE_SPLIT2>, cudaFuncAttributeMaxDynamicSharedMemorySize, HG_SMEM);
    cudaFuncSetAttribute(hmma_gemm<TE_BIAS_RESID_CVT1>, cudaFuncAttributeMaxDynamicSharedMemorySize, HG_SMEM);
    cudaFuncSetAttribute(hmma_gemm<TE_BIAS_RELU_CVT16>, cudaFuncAttributeMaxDynamicSharedMemorySize, HG_SMEM);
    cudaFuncSetAttribute(hmma_gemm<TE_GATED_RED>, cudaFuncAttributeMaxDynamicSharedMemorySize, HG_SMEM);

    PtrArr bnone = {};
    dim3 blk(256);

    // 1. input / weight conversions
    cvt16<<<(MT * HH / 4) / 256, blk>>>(x, x16);
    {
        PtrArr wi; wi.p[0] = Wq; wi.p[1] = Wk; wi.p[2] = Wv;
        transpose_split<1><<<dim3(HH / 64, HH / 64, 3), blk>>>(wi, HH, HH, wqkv1, (long long)HH * HH);
    }
    {
        PtrArr wi; wi.p[0] = Wo;
        transpose_split<2><<<dim3(HH / 64, HH / 64, 1), blk>>>(wi, HH, HH, wo2, 0);
    }
    {
        PtrArr wi;
        for (int e = 0; e < 8; e++) wi.p[e] = W1 + (long long)e * HH * DD;
        transpose_split<1><<<dim3(DD / 64, HH / 64, EE), blk>>>(wi, HH, DD, w1ts, (long long)HH * DD);
    }
    {
        PtrArr wi;
        for (int e = 0; e < 8; e++) wi.p[e] = W2 + (long long)e * DD * HH;
        transpose_split<1><<<dim3(HH / 64, DD / 64, EE), blk>>>(wi, DD, HH, w2ts, (long long)DD * HH);
    }

    // 2. QKV projections (batched z=3, 1-term) -> fp16 only
    {
        PtrArr ba; ba.p[0] = bq; ba.p[1] = bk; ba.p[2] = bv;
        hmma_gemm<TE_BIAS_CVT16><<<dim3(HH / 128, MT / 128, 3), blk, HG_SMEM>>>(
            x16, 0, wqkv1, (long long)HH * HH, HH, nullptr, 0, ba,
            nullptr, qkv16, (long long)MT * HH, HH, nullptr, 0.0f);
    }
    const __half* q16 = qkv16;
    const __half* k16 = qkv16 + (long long)MT * HH;
    const __half* v16 = qkv16 + 2LL * MT * HH;

    // 3. attention core
    hmma_gemm<TE_SCALE><<<dim3(SQ / 128, SQ / 128, BB), blk, HG_SMEM>>>(
        q16, (long long)SQ * HH, k16, (long long)SQ * HH, HH,
        s, (long long)SQ * SQ, bnone, nullptr, nullptr, 0, 0, nullptr, 0.03125f);
    softmax_rows<<<BB * SQ, 256>>>(s, ps);
    transpose_h<<<dim3(HH / 64, SQ / 64, BB), blk>>>(
        v16, (long long)SQ * HH, vts, (long long)HH * SQ, SQ, HH);
    // PV -> a 2-term split directly
    hmma_gemm<TE_SPLIT2><<<dim3(HH / 128, SQ / 128, BB), blk, HG_SMEM>>>(
        ps, (long long)SQ * SQ, vts, (long long)HH * SQ, SQ,
        nullptr, 0, bnone, nullptr, as2, (long long)SQ * 2 * HH, HH, nullptr, 0.0f);

    // 4. O projection (2-term) + residual -> x2 fp32 + x2s fp16
    {
        PtrArr ba; ba.p[0] = bo;
        hmma_gemm<TE_BIAS_RESID_CVT1><<<dim3(HH / 128, MT / 128, 1), blk, HG_SMEM>>>(
            as2, 0, wo2, 0, 2 * HH, x2, 0, ba, x, x2s, 0, HH, nullptr, 0.0f);
    }

    // 5. fused gates + output base
    gates_out<<<MT, 256>>>(x2, Wg, bg, b2, g, out);

    // 6. expert up-proj (batched z=8, fp16)
    {
        PtrArr ba;
        for (int e = 0; e < 8; e++) ba.p[e] = b1 + (long long)e * DD;
        hmma_gemm<TE_BIAS_RELU_CVT16><<<dim3(DD / 128, MT / 128, EE), blk, HG_SMEM>>>(
            x2s, 0, w1ts, (long long)HH * DD, HH, nullptr, 0, ba, nullptr,
            hs, (long long)MT * DD, DD, nullptr, 0.0f);
    }

    // 7. expert down-proj (batched z=8, fp16) with fused gated accumulation
    hmma_gemm<TE_GATED_RED><<<dim3(HH / 128, MT / 128, EE), blk, HG_SMEM>>>(
        hs, (long long)MT * DD, w2ts, (long long)DD * HH, DD, out, 0, bnone,
        nullptr, nullptr, 0, 0, g, 0.0f);
}

// round 14
// speedup vs baseline: 6.3914x; 1.0306x over previous
#include <cuda_runtime.h>
#include <cuda_bf16.h>
#include <cuda_fp16.h>
#include <cstdint>

// ============================================================================
// TinyTransformerBlock on GB300 (compute_103 PTX -> HMMA fp16 tensor cores).
//  - QKV projection:  1-term fp16
//  - Attention:       fp16 HMMA, fp16 scores, shuffle softmax
//  - O projection:    1-term fp16 (a's own error already fp16-scale)
//  - MoE up/down:     fp16, gating fused via atomic RED.ADD
// fp32 accumulation in all HMMA. Softmax/gates math fp32.
// ============================================================================

__device__ __forceinline__ uint32_t smem_to_u32(const void* p) {
    uint32_t a;
    asm("{ .reg .u64 t; cvta.to.shared.u64 t, %1; cvt.u32.u64 %0, t; }" : "=r"(a) : "l"(p));
    return a;
}
__device__ __forceinline__ void cp16(uint32_t saddr, const void* g) {
    asm volatile("cp.async.cg.shared.global [%0], [%1], 16;" :: "r"(saddr), "l"(g));
}
#define CP_COMMIT() asm volatile("cp.async.commit_group;" ::: "memory")
#define CP_WAIT_1() asm volatile("cp.async.wait_group 1;" ::: "memory")

__device__ __forceinline__ void ldm_x4(uint32_t* r, uint32_t addr) {
    asm volatile("ldmatrix.sync.aligned.m8n8.x4.shared.b16 {%0,%1,%2,%3}, [%4];"
        : "=r"(r[0]), "=r"(r[1]), "=r"(r[2]), "=r"(r[3]) : "r"(addr));
}
__device__ __forceinline__ void mma_16816(float* c, const uint32_t* a, uint32_t b0, uint32_t b1) {
    asm volatile("mma.sync.aligned.m16n8k16.row.col.f32.f16.f16.f32 "
        "{%0,%1,%2,%3}, {%4,%5,%6,%7}, {%8,%9}, {%0,%1,%2,%3};"
        : "+f"(c[0]), "+f"(c[1]), "+f"(c[2]), "+f"(c[3])
        : "r"(a[0]), "r"(a[1]), "r"(a[2]), "r"(a[3]), "r"(b0), "r"(b1));
}

// ---------------- problem sizes ----------------
#define MT 4096
#define HH 1024
#define DD 4096
#define EE 8
#define SQ 1024
#define BB 4

// ---------------- scratch (device globals; allocation-free) ----------------
__device__ __align__(1024) float g_x2[(long long)MT * HH];
__device__ __align__(1024) float g_g[(long long)MT * EE];
__device__ __align__(1024) __half g_x16[(long long)MT * HH];
__device__ __align__(1024) __half g_qkv16[3ULL * MT * HH];
__device__ __align__(1024) __half g_s16[(long long)BB * SQ * SQ];     // fp16 scores
__device__ __align__(1024) __half g_ps[(long long)MT * SQ];           // fp16 probs
__device__ __align__(1024) __half g_vts[(long long)BB * HH * SQ];     // V^T fp16
__device__ __align__(1024) __half g_a16[(long long)MT * HH];          // a fp16
__device__ __align__(1024) __half g_x2s[(long long)MT * HH];          // x2 fp16
__device__ __align__(1024) __half g_wqkvo[4ULL * HH * HH];            // Wq,Wk,Wv,Wo fp16^T
__device__ __align__(1024) __half g_w1ts[(long long)EE * DD * HH];
__device__ __align__(1024) __half g_w2ts[(long long)EE * HH * DD];
__device__ __align__(1024) __half g_hs[(long long)EE * MT * DD];

struct PtrArr { const float* p[8]; };

// ---------------- HMMA GEMM ----------------
enum { TE_BIAS_CVT16 = 0,      // bias, fp16 store (QKV)
       TE_SCALE_CVT16 = 1,     // *alpha, fp16 store (scores)
       TE_CVT16 = 2,           // raw acc, fp16 store (a)
       TE_BIAS_RESID_CVT1 = 3, // bias+resid, fp32 + fp16 store (x2)
       TE_BIAS_RELU_CVT16 = 4, // bias+relu, fp16 store (hs)
       TE_GATED_RED = 5 };     // gate*acc atomically into out

#define HG_STAGE 32768
#define HG_SMEM (3 * HG_STAGE)

__device__ __forceinline__ void load_tile_cp(uint32_t sbase, const __half* g,
                                             long long ld, int row0, int k0, int tid)
{
    const int r = tid >> 1;
    const int c0 = (tid & 1) * 4;
    const __half* gp = g + (long long)(row0 + r) * ld + k0 + c0 * 8;
    const uint32_t srow = sbase + r * 128;
#pragma unroll
    for (int i = 0; i < 4; i++)
        cp16(srow + (((c0 + i) ^ (r & 7)) << 4), gp + i * 8);
}

template <int EPI>
__global__ void __launch_bounds__(256)
hmma_gemm(const __half* __restrict__ A, long long aZ,
          const __half* __restrict__ B, long long bZ,
          int Kp, float* C, long long cZ, PtrArr bias, const float* resid,
          __half* cvt, long long cvtZ, int cvtK,
          const float* __restrict__ gate, float alpha)
{
    extern __shared__ __align__(1024) char smem[];
    const uint32_t sb = smem_to_u32(smem);
    const int tid = threadIdx.x;
    const int wid = tid >> 5, lane = tid & 31;
    const int z = blockIdx.z;
    const int m0 = blockIdx.y << 7;
    const int n0 = blockIdx.x << 7;
    const int Nt = gridDim.x << 7;
    const __half* Az = A + (long long)z * aZ;
    const __half* Bz = B + (long long)z * bZ;
    const int nch = Kp >> 6;

    const int wm = (wid >> 2) * 64;
    const int wn = (wid & 3) * 32;

    float acc[4][4][4];
#pragma unroll
    for (int i = 0; i < 4; i++)
#pragma unroll
        for (int j = 0; j < 4; j++)
#pragma unroll
            for (int r = 0; r < 4; r++) acc[i][j][r] = 0.0f;

    load_tile_cp(sb, Az, Kp, m0, 0, tid);
    load_tile_cp(sb + 16384, Bz, Kp, n0, 0, tid);
    CP_COMMIT();
    load_tile_cp(sb + HG_STAGE, Az, Kp, m0, 64, tid);
    load_tile_cp(sb + HG_STAGE + 16384, Bz, Kp, n0, 64, tid);
    CP_COMMIT();

    const int arow = lane & 15;
    const int ahalf = lane >> 4;
    const int brow = (lane & 7) + ((lane >> 4) & 1) * 8;
    const int bhalf = (lane >> 3) & 1;

    for (int c = 0; c < nch; c++) {
        CP_WAIT_1();
        __syncthreads();
        if (c + 2 < nch) {
            const uint32_t st = sb + ((c + 2) % 3) * HG_STAGE;
            load_tile_cp(st, Az, Kp, m0, (c + 2) * 64, tid);
            load_tile_cp(st + 16384, Bz, Kp, n0, (c + 2) * 64, tid);
        }
        CP_COMMIT();

        const uint32_t sA = sb + (c % 3) * HG_STAGE;
        const uint32_t sB = sA + 16384;
#pragma unroll
        for (int ks = 0; ks < 4; ks++) {
            uint32_t a[4][4];
#pragma unroll
            for (int mi = 0; mi < 4; mi++) {
                const int row = wm + mi * 16 + arow;
                const int ch = ks * 2 + ahalf;
                ldm_x4(a[mi], sA + row * 128 + ((ch ^ (row & 7)) << 4));
            }
            uint32_t b[2][4];
#pragma unroll
            for (int gI = 0; gI < 2; gI++) {
                const int row = wn + gI * 16 + brow;
                const int ch = ks * 2 + bhalf;
                ldm_x4(b[gI], sB + row * 128 + ((ch ^ (row & 7)) << 4));
            }
#pragma unroll
            for (int mi = 0; mi < 4; mi++)
#pragma unroll
                for (int ni = 0; ni < 4; ni++) {
                    const int gI = ni >> 1, off = (ni & 1) * 2;
                    mma_16816(acc[mi][ni], a[mi], b[gI][off], b[gI][off + 1]);
                }
        }
        __syncthreads();
    }

    // ---- epilogue ----
    const int l4 = lane >> 2, l2 = (lane & 3) << 1;
    float* Cz = C ? C + (long long)z * cZ : nullptr;
    const float* bz = bias.p[z];
    __half* cvz = cvt ? cvt + (long long)z * cvtZ : nullptr;

#pragma unroll
    for (int mi = 0; mi < 4; mi++)
#pragma unroll
        for (int h = 0; h < 2; h++) {
            const long long m = (long long)m0 + wm + mi * 16 + l4 + h * 8;
            float ge = 0.0f;
            if (EPI == TE_GATED_RED) ge = gate[m * EE + z];
#pragma unroll
            for (int ni = 0; ni < 4; ni++) {
                const long long n = n0 + wn + ni * 8 + l2;
                float v0 = acc[mi][ni][h * 2 + 0];
                float v1 = acc[mi][ni][h * 2 + 1];
                if (EPI == TE_BIAS_CVT16 || EPI == TE_BIAS_RESID_CVT1 ||
                    EPI == TE_BIAS_RELU_CVT16) {
                    v0 += bz[n]; v1 += bz[n + 1];
                }
                if (EPI == TE_SCALE_CVT16) { v0 *= alpha; v1 *= alpha; }
                if (EPI == TE_BIAS_RELU_CVT16) {
                    v0 = fmaxf(v0, 0.0f); v1 = fmaxf(v1, 0.0f);
                }
                if (EPI == TE_BIAS_RESID_CVT1) {
                    float2 rv = *(const float2*)&resid[m * Nt + n];
                    v0 += rv.x; v1 += rv.y;
                }
                if (EPI == TE_BIAS_RESID_CVT1) {
                    float2 o; o.x = v0; o.y = v1;
                    *(float2*)&Cz[m * Nt + n] = o;
                }
                if (EPI == TE_GATED_RED) {
                    atomicAdd(&Cz[m * Nt + n], ge * v0);
                    atomicAdd(&Cz[m * Nt + n + 1], ge * v1);
                }
                if (EPI != TE_GATED_RED) {
                    *(__half2*)&cvz[m * cvtK + n] =
                        __halves2half2(__float2half_rn(v0), __float2half_rn(v1));
                }
            }
        }
}

// ---------------- aux kernels ----------------
__global__ void cvt16(const float* __restrict__ in, __half* __restrict__ out)
{
    const long long i = (long long)blockIdx.x * blockDim.x + threadIdx.x;
    float4 v = ((const float4*)in)[i];
    __half2 a = __floats2half2_rn(v.x, v.y);
    __half2 b = __floats2half2_rn(v.z, v.w);
    uint2 u; u.x = *(uint32_t*)&a; u.y = *(uint32_t*)&b;
    ((uint2*)out)[i] = u;
}

// transpose+convert: in [K,N] fp32 -> out [N,K] fp16
__global__ void transpose_cvt(PtrArr in, int K, int N,
                              __half* __restrict__ out, long long outZ)
{
    __shared__ float t[64][65];
    const float* src = in.p[blockIdx.z];
    __half* dst = out + blockIdx.z * outZ;
    const int n0 = blockIdx.x * 64, k0 = blockIdx.y * 64;
    const int lr = threadIdx.x >> 4;
    const int lc = (threadIdx.x & 15) * 4;
#pragma unroll
    for (int j = 0; j < 4; j++) {
        const int r = lr + j * 16;
        float4 v = *(const float4*)&src[(long long)(k0 + r) * N + n0 + lc];
        t[r][lc] = v.x; t[r][lc + 1] = v.y; t[r][lc + 2] = v.z; t[r][lc + 3] = v.w;
    }
    __syncthreads();
    const int orow = threadIdx.x >> 2;
    const int oc = threadIdx.x & 3;
    __half* obase = dst + (long long)(n0 + orow) * K + k0;
#pragma unroll
    for (int j = 0; j < 4; j++) {
        const int kq = (oc + j * 4) * 4;
        __half2 a = __floats2half2_rn(t[kq][orow], t[kq + 1][orow]);
        __half2 b = __floats2half2_rn(t[kq + 2][orow], t[kq + 3][orow]);
        uint2 u; u.x = *(uint32_t*)&a; u.y = *(uint32_t*)&b;
        *(uint2*)&obase[kq] = u;
    }
}

// fp16 transpose: in [K,N] -> out [N,K]
__global__ void transpose_h(const __half* __restrict__ in, long long inZ,
                            __half* __restrict__ out, long long outZ, int K, int N)
{
    __shared__ __half t[64][66];
    const __half* src = in + blockIdx.z * inZ;
    __half* dst = out + blockIdx.z * outZ;
    const int n0 = blockIdx.x * 64, k0 = blockIdx.y * 64;
    const int lr = threadIdx.x >> 4;
    const int lc = (threadIdx.x & 15) * 4;
#pragma unroll
    for (int j = 0; j < 4; j++) {
        const int r = lr + j * 16;
        uint2 v = *(const uint2*)&src[(long long)(k0 + r) * N + n0 + lc];
        *(__half2*)&t[r][lc] = *(__half2*)&v.x;
        *(__half2*)&t[r][lc + 2] = *(__half2*)&v.y;
    }
    __syncthreads();
    const int orow = threadIdx.x >> 2;
    const int oc = threadIdx.x & 3;
    __half* obase = dst + (long long)(n0 + orow) * K + k0;
#pragma unroll
    for (int j = 0; j < 4; j++) {
        const int kq = (oc + j * 4) * 4;
        __half2 a = __halves2half2(t[kq][orow], t[kq + 1][orow]);
        __half2 b = __halves2half2(t[kq + 2][orow], t[kq + 3][orow]);
        uint2 u; u.x = *(uint32_t*)&a; u.y = *(uint32_t*)&b;
        *(uint2*)&obase[kq] = u;
    }
}

// shuffle softmax: 1024 cols fp16 in, fp16 probs out
__global__ void softmax_rows(const __half* __restrict__ S, __half* __restrict__ P)
{
    const int row = blockIdx.x, tid = threadIdx.x;
    const int lane = tid & 31, wid = tid >> 5;
    uint2 u = ((const uint2*)(S + (long long)row * SQ))[tid];
    __half2 h01 = *(__half2*)&u.x, h23 = *(__half2*)&u.y;
    float v0 = __low2float(h01), v1 = __high2float(h01);
    float v2 = __low2float(h23), v3 = __high2float(h23);
    float m = fmaxf(fmaxf(v0, v1), fmaxf(v2, v3));
#pragma unroll
    for (int o = 16; o; o >>= 1) m = fmaxf(m, __shfl_xor_sync(0xFFFFFFFFu, m, o));
    __shared__ float wm[8], ws[8];
    if (lane == 0) wm[wid] = m;
    __syncthreads();
    m = wm[0];
#pragma unroll
    for (int w = 1; w < 8; w++) m = fmaxf(m, wm[w]);
    float e0 = __expf(v0 - m), e1 = __expf(v1 - m);
    float e2 = __expf(v2 - m), e3 = __expf(v3 - m);
    float sum = e0 + e1 + e2 + e3;
#pragma unroll
    for (int o = 16; o; o >>= 1) sum += __shfl_xor_sync(0xFFFFFFFFu, sum, o);
    if (lane == 0) ws[wid] = sum;
    __syncthreads();
    sum = 0.0f;
#pragma unroll
    for (int w = 0; w < 8; w++) sum += ws[w];
    const float inv = 1.0f / sum;
    __half2 a = __floats2half2_rn(e0 * inv, e1 * inv);
    __half2 b = __floats2half2_rn(e2 * inv, e3 * inv);
    uint2 o2; o2.x = *(uint32_t*)&a; o2.y = *(uint32_t*)&b;
    ((uint2*)(P + (long long)row * SQ))[tid] = o2;
}

// fused gates + output base, shuffle reductions
__global__ void gates_out(const float* __restrict__ x2, const float* __restrict__ Wg,
                          const float* __restrict__ bg, const float* __restrict__ b2,
                          float* __restrict__ G, float* __restrict__ out)
{
    const int row = blockIdx.x, tid = threadIdx.x;
    const int lane = tid & 31, wid = tid >> 5;
    float4 xv = ((const float4*)(x2 + (long long)row * HH))[tid];
    float xa[4] = {xv.x, xv.y, xv.z, xv.w};
    float part[8];
#pragma unroll
    for (int e = 0; e < 8; e++) part[e] = 0.0f;
    const float* w = Wg + (long long)tid * 4 * 8;
#pragma unroll
    for (int i = 0; i < 4; i++)
#pragma unroll
        for (int e = 0; e < 8; e++)
            part[e] = fmaf(xa[i], w[i * 8 + e], part[e]);
#pragma unroll
    for (int e = 0; e < 8; e++)
#pragma unroll
        for (int o = 16; o; o >>= 1)
            part[e] += __shfl_xor_sync(0xFFFFFFFFu, part[e], o);
    __shared__ float wsum[8][9];
    if (lane == 0) {
#pragma unroll
        for (int e = 0; e < 8; e++) wsum[wid][e] = part[e];
    }
    __syncthreads();
    __shared__ float gsh[8];
    if (tid < 8) {
        float v = 0.0f;
#pragma unroll
        for (int w8 = 0; w8 < 8; w8++) v += wsum[w8][tid];
        gsh[tid] = v + bg[tid];
    }
    __syncthreads();
    if (tid == 0) {
        float m = -1e30f;
#pragma unroll
        for (int e = 0; e < 8; e++) m = fmaxf(m, gsh[e]);
        float ex[8], s = 0.0f;
#pragma unroll
        for (int e = 0; e < 8; e++) { ex[e] = __expf(gsh[e] - m); s += ex[e]; }
        const float inv = 1.0f / s;
#pragma unroll
        for (int e = 0; e < 8; e++) gsh[e] = ex[e] * inv;
    }
    __syncthreads();
    if (tid < 8) G[row * 8 + tid] = gsh[tid];
    float4 acc = xv;
#pragma unroll
    for (int e = 0; e < 8; e++) {
        const float ge = gsh[e];
        float4 b = ((const float4*)(b2 + e * HH))[tid];
        acc.x = fmaf(ge, b.x, acc.x); acc.y = fmaf(ge, b.y, acc.y);
        acc.z = fmaf(ge, b.z, acc.z); acc.w = fmaf(ge, b.w, acc.w);
    }
    ((float4*)(out + (long long)row * HH))[tid] = acc;
}

// ---------------- host side ----------------
extern "C" void kernel_launch(void* const* d_in, const int* in_sizes, int n_in,
                              void* d_out, int out_size)
{
    const float* x  = (const float*)d_in[0];
    const float* Wq = (const float*)d_in[1];
    const float* bq = (const float*)d_in[2];
    const float* Wk = (const float*)d_in[3];
    const float* bk = (const float*)d_in[4];
    const float* Wv = (const float*)d_in[5];
    const float* bv = (const float*)d_in[6];
    const float* Wo = (const float*)d_in[7];
    const float* bo = (const float*)d_in[8];
    const float* Wg = (const float*)d_in[9];
    const float* bg = (const float*)d_in[10];
    const float* W1 = (const float*)d_in[11];
    const float* b1 = (const float*)d_in[12];
    const float* W2 = (const float*)d_in[13];
    const float* b2 = (const float*)d_in[14];
    float* out = (float*)d_out;

    float *x2, *g;
    __half *x16, *qkv16, *s16, *ps, *vts, *a16, *x2s, *wqkvo, *w1ts, *w2ts, *hs;
    cudaGetSymbolAddress((void**)&x2, g_x2);
    cudaGetSymbolAddress((void**)&g, g_g);
    cudaGetSymbolAddress((void**)&x16, g_x16);
    cudaGetSymbolAddress((void**)&qkv16, g_qkv16);
    cudaGetSymbolAddress((void**)&s16, g_s16);
    cudaGetSymbolAddress((void**)&ps, g_ps);
    cudaGetSymbolAddress((void**)&vts, g_vts);
    cudaGetSymbolAddress((void**)&a16, g_a16);
    cudaGetSymbolAddress((void**)&x2s, g_x2s);
    cudaGetSymbolAddress((void**)&wqkvo, g_wqkvo);
    cudaGetSymbolAddress((void**)&w1ts, g_w1ts);
    cudaGetSymbolAddress((void**)&w2ts, g_w2ts);
    cudaGetSymbolAddress((void**)&hs, g_hs);

    cudaFuncSetAttribute(hmma_gemm<TE_BIAS_CVT16>, cudaFuncAttributeMaxDynamicSharedMemorySize, HG_SMEM);
    cudaFuncSetAttribute(hmma_gemm<TE_SCALE_CVT16>, cudaFuncAttributeMaxDynamicSharedMemorySize, HG_SMEM);
    cudaFuncSetAttribute(hmma_gemm<TE_CVT16>, cudaFuncAttributeMaxDynamicSharedMemorySize, HG_SMEM);
    cudaFuncSetAttribute(hmma_gemm<TE_BIAS_RESID_CVT1>, cudaFuncAttributeMaxDynamicSharedMemorySize, HG_SMEM);
    cudaFuncSetAttribute(hmma_gemm<TE_BIAS_RELU_CVT16>, cudaFuncAttributeMaxDynamicSharedMemorySize, HG_SMEM);
    cudaFuncSetAttribute(hmma_gemm<TE_GATED_RED>, cudaFuncAttributeMaxDynamicSharedMemorySize, HG_SMEM);

    PtrArr bnone = {};
    dim3 blk(256);

    // 1. conversions: x -> fp16; Wq,Wk,Wv,Wo / W1 / W2 -> fp16 transposed
    cvt16<<<(MT * HH / 4) / 256, blk>>>(x, x16);
    {
        PtrArr wi; wi.p[0] = Wq; wi.p[1] = Wk; wi.p[2] = Wv; wi.p[3] = Wo;
        transpose_cvt<<<dim3(HH / 64, HH / 64, 4), blk>>>(wi, HH, HH, wqkvo, (long long)HH * HH);
    }
    {
        PtrArr wi;
        for (int e = 0; e < 8; e++) wi.p[e] = W1 + (long long)e * HH * DD;
        transpose_cvt<<<dim3(DD / 64, HH / 64, EE), blk>>>(wi, HH, DD, w1ts, (long long)HH * DD);
    }
    {
        PtrArr wi;
        for (int e = 0; e < 8; e++) wi.p[e] = W2 + (long long)e * DD * HH;
        transpose_cvt<<<dim3(HH / 64, DD / 64, EE), blk>>>(wi, DD, HH, w2ts, (long long)DD * HH);
    }

    // 2. QKV projections (batched z=3) -> fp16
    {
        PtrArr ba; ba.p[0] = bq; ba.p[1] = bk; ba.p[2] = bv;
        hmma_gemm<TE_BIAS_CVT16><<<dim3(HH / 128, MT / 128, 3), blk, HG_SMEM>>>(
            x16, 0, wqkvo, (long long)HH * HH, HH, nullptr, 0, ba,
            nullptr, qkv16, (long long)MT * HH, HH, nullptr, 0.0f);
    }
    const __half* q16 = qkv16;
    const __half* k16 = qkv16 + (long long)MT * HH;
    const __half* v16 = qkv16 + 2LL * MT * HH;

    // 3. attention core (fp16 scores)
    hmma_gemm<TE_SCALE_CVT16><<<dim3(SQ / 128, SQ / 128, BB), blk, HG_SMEM>>>(
        q16, (long long)SQ * HH, k16, (long long)SQ * HH, HH,
        nullptr, 0, bnone, nullptr, s16, (long long)SQ * SQ, SQ, nullptr, 0.03125f);
    softmax_rows<<<BB * SQ, 256>>>(s16, ps);
    transpose_h<<<dim3(HH / 64, SQ / 64, BB), blk>>>(
        v16, (long long)SQ * HH, vts, (long long)HH * SQ, SQ, HH);
    hmma_gemm<TE_CVT16><<<dim3(HH / 128, SQ / 128, BB), blk, HG_SMEM>>>(
        ps, (long long)SQ * SQ, vts, (long long)HH * SQ, SQ,
        nullptr, 0, bnone, nullptr, a16, (long long)SQ * HH, HH, nullptr, 0.0f);

    // 4. O projection (1-term) + residual -> x2 fp32 + x2s fp16
    {
        PtrArr ba; ba.p[0] = bo;
        hmma_gemm<TE_BIAS_RESID_CVT1><<<dim3(HH / 128, MT / 128, 1), blk, HG_SMEM>>>(
            a16, 0, wqkvo + 3ULL * HH * HH, 0, HH, x2, 0, ba, x, x2s, 0, HH,
            nullptr, 0.0f);
    }

    // 5. fused gates + output base
    gates_out<<<MT, 256>>>(x2, Wg, bg, b2, g, out);

    // 6. expert up-proj (batched z=8)
    {
        PtrArr ba;
        for (int e = 0; e < 8; e++) ba.p[e] = b1 + (long long)e * DD;
        hmma_gemm<TE_BIAS_RELU_CVT16><<<dim3(DD / 128, MT / 128, EE), blk, HG_SMEM>>>(
            x2s, 0, w1ts, (long long)HH * DD, HH, nullptr, 0, ba, nullptr,
            hs, (long long)MT * DD, DD, nullptr, 0.0f);
    }

    // 7. expert down-proj (batched z=8) with fused gated accumulation
    hmma_gemm<TE_GATED_RED><<<dim3(HH / 128, MT / 128, EE), blk, HG_SMEM>>>(
        hs, (long long)MT * DD, w2ts, (long long)DD * HH, DD, out, 0, bnone,
        nullptr, nullptr, 0, 0, g, 0.0f);
}